// round 13
// baseline (speedup 1.0000x reference)
#include <cuda_runtime.h>
#include <cuda_fp16.h>
#include <cstdint>
#include <math.h>

#define RES 7
#define SAMP 14
#define C_CH 256
#define B_SZ 4
#define N_ROI 512
#define M_TOT 2048
#define K1 12544
#define FC 1024
#define OUT_D 100
#define NP 128          // padded heads output dim

// ======================= scratch =======================
__device__ float g_f0[(size_t)B_SZ * 128 * 128 * C_CH];
__device__ float g_f1[(size_t)B_SZ * 64 * 64 * C_CH];
__device__ float g_f2[(size_t)B_SZ * 32 * 32 * C_CH];
__device__ __half g_Xh[(size_t)M_TOT * K1];
__device__ __half g_W1h[(size_t)K1 * FC];    // [K][N], single fp16
__device__ __half g_W2hi[(size_t)FC * FC];
__device__ __half g_W2lo[(size_t)FC * FC];
__device__ __half g_A2h[(size_t)M_TOT * FC];
__device__ float g_Y1[(size_t)M_TOT * FC];
__device__ float g_Y2[(size_t)M_TOT * FC];
__device__ float g_s[FC];                    // BN scale
__device__ float g_t[FC];                    // BN shift
__device__ float g_Wcat[(size_t)FC * NP];    // concat heads weights
__device__ float g_bcat[NP];
__device__ float g_hp[8][M_TOT][NP];         // heads k-split partials

// ======================= streams/events (created at load; no device-mem delta) ===
static cudaStream_t s_aux1, s_aux2;
static cudaEvent_t  e_w1, e_wall, e_roiA, e_g1A;
struct StreamInit {
    StreamInit() {
        cudaStreamCreateWithFlags(&s_aux1, cudaStreamNonBlocking);
        cudaStreamCreateWithFlags(&s_aux2, cudaStreamNonBlocking);
        cudaEventCreateWithFlags(&e_w1,   cudaEventDisableTiming);
        cudaEventCreateWithFlags(&e_wall, cudaEventDisableTiming);
        cudaEventCreateWithFlags(&e_roiA, cudaEventDisableTiming);
        cudaEventCreateWithFlags(&e_g1A,  cudaEventDisableTiming);
    }
};
static StreamInit s_init;

// ======================= small PTX helpers =======================
__device__ __forceinline__ uint32_t smem_u32(const void* p) {
    uint32_t a;
    asm("{ .reg .u64 t; cvta.to.shared.u64 t, %1; cvt.u32.u64 %0, t; }" : "=r"(a) : "l"(p));
    return a;
}
__device__ __forceinline__ void cp_async16(uint32_t dst, const void* src) {
    asm volatile("cp.async.cg.shared.global [%0], [%1], 16;" :: "r"(dst), "l"(src));
}
__device__ __forceinline__ void cp_commit() { asm volatile("cp.async.commit_group;"); }
template <int N> __device__ __forceinline__ void cp_wait() {
    asm volatile("cp.async.wait_group %0;" :: "n"(N));
}
__device__ __forceinline__ void ldsm_x4(uint32_t r[4], uint32_t addr) {
    asm volatile("ldmatrix.sync.aligned.m8n8.x4.shared.b16 {%0,%1,%2,%3}, [%4];"
                 : "=r"(r[0]), "=r"(r[1]), "=r"(r[2]), "=r"(r[3]) : "r"(addr));
}
__device__ __forceinline__ void ldsm_x4_t(uint32_t r[4], uint32_t addr) {
    asm volatile("ldmatrix.sync.aligned.m8n8.x4.trans.shared.b16 {%0,%1,%2,%3}, [%4];"
                 : "=r"(r[0]), "=r"(r[1]), "=r"(r[2]), "=r"(r[3]) : "r"(addr));
}
__device__ __forceinline__ void mma16816(float c[4], const uint32_t a[4], const uint32_t b[2]) {
    asm volatile("mma.sync.aligned.m16n8k16.row.col.f32.f16.f16.f32 "
                 "{%0,%1,%2,%3}, {%4,%5,%6,%7}, {%8,%9}, {%0,%1,%2,%3};"
                 : "+f"(c[0]), "+f"(c[1]), "+f"(c[2]), "+f"(c[3])
                 : "r"(a[0]), "r"(a[1]), "r"(a[2]), "r"(a[3]), "r"(b[0]), "r"(b[1]));
}

// ======================= NCHW -> NHWC =======================
__global__ void transpose_nchw_nhwc(const float* __restrict__ in,
                                    float* __restrict__ out, int HW) {
    __shared__ float tile[32][33];
    int b  = blockIdx.z;
    int s0 = blockIdx.x * 32;
    int c0 = blockIdx.y * 32;
    int tx = threadIdx.x, ty = threadIdx.y;
    const float* inb = in + (size_t)b * C_CH * HW;
    float* outb = out + (size_t)b * HW * C_CH;
#pragma unroll
    for (int i = 0; i < 32; i += 8)
        tile[ty + i][tx] = inb[(size_t)(c0 + ty + i) * HW + s0 + tx];
    __syncthreads();
#pragma unroll
    for (int i = 0; i < 32; i += 8)
        outb[(size_t)(s0 + ty + i) * C_CH + c0 + tx] = tile[tx][ty + i];
}

// ======================= W fp32 -> fp16 (single) =======================
__global__ void w_to_h4(const float4* __restrict__ in, __half2* __restrict__ out, int total4) {
    int i = blockIdx.x * blockDim.x + threadIdx.x;
    if (i >= total4) return;
    float4 v = in[i];
    out[2 * i]     = __floats2half2_rn(v.x, v.y);
    out[2 * i + 1] = __floats2half2_rn(v.z, v.w);
}

// ======================= W fp32 -> hi/lo fp16 =======================
__global__ void split_w4(const float4* __restrict__ in, __half2* __restrict__ hi,
                         __half2* __restrict__ lo, int total4) {
    int i = blockIdx.x * blockDim.x + threadIdx.x;
    if (i >= total4) return;
    float4 v = in[i];
    __half hx = __float2half_rn(v.x), hy = __float2half_rn(v.y);
    __half hz = __float2half_rn(v.z), hw = __float2half_rn(v.w);
    hi[2 * i]     = __halves2half2(hx, hy);
    hi[2 * i + 1] = __halves2half2(hz, hw);
    lo[2 * i]     = __halves2half2(__float2half_rn(v.x - __half2float(hx)),
                                   __float2half_rn(v.y - __half2float(hy)));
    lo[2 * i + 1] = __halves2half2(__float2half_rn(v.z - __half2float(hz)),
                                   __float2half_rn(v.w - __half2float(hw)));
}

// ======================= concat heads weights =======================
__global__ void concat_heads(const float* __restrict__ cw,  const float* __restrict__ cb,
                             const float* __restrict__ bw,  const float* __restrict__ bb_,
                             const float* __restrict__ ycw, const float* __restrict__ ycb,
                             const float* __restrict__ yrw, const float* __restrict__ yrb,
                             const float* __restrict__ hw,  const float* __restrict__ hb) {
    int idx = blockIdx.x * blockDim.x + threadIdx.x;
    if (idx >= FC * NP) return;
    int k = idx >> 7, n = idx & 127;
    float v = 0.f;
    if (n < 4)        v = cw [k * 4  + n];
    else if (n < 22)  v = bw [k * 18 + n - 4];
    else if (n < 58)  v = ycw[k * 36 + n - 22];
    else if (n < 94)  v = yrw[k * 36 + n - 58];
    else if (n < 100) v = hw [k * 6  + n - 94];
    g_Wcat[idx] = v;
    if (k == 0) {
        float bv = 0.f;
        if (n < 4)        bv = cb [n];
        else if (n < 22)  bv = bb_[n - 4];
        else if (n < 58)  bv = ycb[n - 22];
        else if (n < 94)  bv = yrb[n - 58];
        else if (n < 100) bv = hb [n - 94];
        g_bcat[n] = bv;
    }
}

// ======================= ROI align (tap dedup) -> X fp16 =======================
__global__ void roi_align_kernel(const float* __restrict__ bbox2d,
                                 const int* __restrict__ anchor, int roiOff) {
    int roi = blockIdx.x + roiOff;
    int b   = roi / N_ROI;
    int tid = threadIdx.x;

    __shared__ int   ax_p0[2][SAMP], ax_p1[2][SAMP];
    __shared__ float ax_l [2][SAMP], ax_v [2][SAMP];
    __shared__ int   cnt [2][7];
    __shared__ int   toff[2][7][4];
    __shared__ float twt [2][7][4];

    int level = anchor[roi] / 3;
    float scale = (level == 0) ? 0.25f : (level == 1) ? 0.125f : 0.0625f;
    int   H     = (level == 0) ? 128   : (level == 1) ? 64     : 32;
    const float* F = (level == 0) ? g_f0 : (level == 1) ? g_f1 : g_f2;
    F += b * H * H * C_CH;

    if (tid < 2 * SAMP) {
        int axis = tid / SAMP;
        int j    = tid % SAMP;
        float cy = bbox2d[roi*4+0], cx = bbox2d[roi*4+1];
        float hh = bbox2d[roi*4+2], ww = bbox2d[roi*4+3];
        float lo_ = (axis == 0) ? (cy - 0.5f*hh) : (cx - 0.5f*ww);
        float hi_ = (axis == 0) ? (cy + 0.5f*hh) : (cx + 0.5f*ww);
        float start = lo_ * scale - 0.5f;
        float bs    = (hi_ - lo_) * scale / (float)RES;
        float g     = ((float)j + 0.5f) * 0.5f;
        float pos   = start + g * bs;
        float valid = (pos > -1.0f && pos < (float)H) ? 1.0f : 0.0f;
        float p  = fminf(fmaxf(pos, 0.0f), (float)(H - 1));
        int  p0  = (int)floorf(p);
        int  p1  = min(p0 + 1, H - 1);
        ax_p0[axis][j] = p0;  ax_p1[axis][j] = p1;
        ax_l [axis][j] = p - (float)p0;
        ax_v [axis][j] = valid;
    }
    __syncthreads();

    if (tid < 14) {
        int axis = tid / 7, p = tid % 7;
        int pos[4]; float wt[4]; int n = 0;
#pragma unroll
        for (int s = 0; s < 2; s++) {
            int j = 2 * p + s;
            int q0 = ax_p0[axis][j], q1 = ax_p1[axis][j];
            float l = ax_l[axis][j], vv = ax_v[axis][j];
            int   cq[2]  = {q0, q1};
            float cwv[2] = {(1.f - l) * vv, l * vv};
#pragma unroll
            for (int e = 0; e < 2; e++) {
                if (cwv[e] == 0.f) continue;
                bool found = false;
                for (int i = 0; i < n; i++)
                    if (pos[i] == cq[e]) { wt[i] += cwv[e]; found = true; break; }
                if (!found) { pos[n] = cq[e]; wt[n] = cwv[e]; n++; }
            }
        }
        int mult = (axis == 0) ? H * C_CH : C_CH;
        float fac = (axis == 0) ? 0.25f : 1.f;
        cnt[axis][p] = n;
        for (int i = 0; i < n; i++) {
            toff[axis][p][i] = pos[i] * mult;
            twt [axis][p][i] = wt[i] * fac;
        }
    }
    __syncthreads();

    int c = tid;
    __half* xrow = g_Xh + (size_t)roi * K1 + c * 49;

#pragma unroll 1
    for (int py = 0; py < 7; py++) {
        int ny = cnt[0][py];
#pragma unroll 1
        for (int px = 0; px < 7; px++) {
            int nx = cnt[1][px];
            float v = 0.f;
            for (int iy = 0; iy < ny; iy++) {
                const float* Fr = F + toff[0][py][iy] + c;
                float wy = twt[0][py][iy];
                for (int ix = 0; ix < nx; ix++)
                    v += wy * twt[1][px][ix] * Fr[toff[1][px][ix]];
            }
            xrow[py * 7 + px] = __float2half_rn(v);
        }
    }
}

// ======================= fp16 HMMA GEMM (NB = #B passes) =======================
#define SA_STRIDE 80               // 32 halves (64B) + 16B pad
#define SB_STRIDE 272              // 128 halves (256B) + 16B pad
#define A_TILE (128 * SA_STRIDE)   // 10240
#define B_TILE (32 * SB_STRIDE)    // 8704

template<int NB>
__global__ void __launch_bounds__(256)
gemm_f16(const __half* __restrict__ A,
         const __half* __restrict__ Whi, const __half* __restrict__ Wlo,
         const float* __restrict__ bias, float* __restrict__ Cc,
         int N, int K, int mOff) {
    constexpr int STAGE = A_TILE + NB * B_TILE;
    extern __shared__ char smem[];
    uint32_t sb = smem_u32(smem);
    int tid = threadIdx.x, wid = tid >> 5, lid = tid & 31;
    int mBase = blockIdx.y * 128 + mOff, nBase = blockIdx.x * 128;
    int kh = wid >> 2;
    int wm = (wid >> 1) & 1, wn = wid & 1;

    float acc[4][8][4];
#pragma unroll
    for (int i = 0; i < 4; i++)
#pragma unroll
        for (int j = 0; j < 8; j++)
#pragma unroll
            for (int q = 0; q < 4; q++) acc[i][j][q] = 0.f;

    const int nIter = K >> 5;

    auto load_stage = [&](int iter, int stage) {
        int k0 = iter * 32;
        uint32_t stBase = sb + stage * STAGE;
#pragma unroll
        for (int i = 0; i < 2; i++) {
            int idx = tid + i * 256;
            int row = idx >> 2, ck = idx & 3;
            cp_async16(stBase + row * SA_STRIDE + ck * 16,
                       A + (size_t)(mBase + row) * K + k0 + ck * 8);
        }
#pragma unroll
        for (int i = 0; i < 2 * NB; i++) {
            int idx = tid + i * 256;
            const __half* src = (NB == 2 && idx >= 512) ? Wlo : Whi;
            int within = idx & 511;
            int row = within >> 4, ck = within & 15;
            cp_async16(stBase + A_TILE + (idx >> 9) * B_TILE + row * SB_STRIDE + ck * 16,
                       src + (size_t)(k0 + row) * N + nBase + ck * 8);
        }
        cp_commit();
    };

    load_stage(0, 0);
    if (nIter > 1) load_stage(1, 1);
    if (nIter > 2) load_stage(2, 2);

    for (int it = 0; it < nIter; it++) {
        int stage = it & 3;
        if (it + 3 < nIter) { load_stage(it + 3, (it + 3) & 3); cp_wait<3>(); }
        else if (it + 2 < nIter) cp_wait<2>();
        else if (it + 1 < nIter) cp_wait<1>();
        else cp_wait<0>();
        __syncthreads();

        uint32_t stBase = sb + stage * STAGE;
        uint32_t aB = stBase;
        uint32_t bHiB = stBase + A_TILE, bLoB = bHiB + B_TILE;

        uint32_t ah[4][4], bh[8][2], bl[8][2];
#pragma unroll
        for (int mt = 0; mt < 4; mt++) {
            uint32_t off = (uint32_t)(wm * 64 + mt * 16 + (lid & 15)) * SA_STRIDE
                         + kh * 32 + (lid >> 4) * 16;
            ldsm_x4(ah[mt], aB + off);
        }
#pragma unroll
        for (int np = 0; np < 4; np++) {
            uint32_t off = (uint32_t)(kh * 16 + (lid & 15)) * SB_STRIDE
                         + (wn * 64 + np * 16 + (lid >> 4) * 8) * 2;
            uint32_t t[4];
            ldsm_x4_t(t, bHiB + off);
            bh[np*2][0] = t[0]; bh[np*2][1] = t[1];
            bh[np*2+1][0] = t[2]; bh[np*2+1][1] = t[3];
            if (NB == 2) {
                ldsm_x4_t(t, bLoB + off);
                bl[np*2][0] = t[0]; bl[np*2][1] = t[1];
                bl[np*2+1][0] = t[2]; bl[np*2+1][1] = t[3];
            }
        }
#pragma unroll
        for (int mt = 0; mt < 4; mt++)
#pragma unroll
            for (int nt = 0; nt < 8; nt++) {
                mma16816(acc[mt][nt], ah[mt], bh[nt]);
                if (NB == 2) mma16816(acc[mt][nt], ah[mt], bl[nt]);
            }
        __syncthreads();
    }

    int tile = wm * 2 + wn;
    float* ep = (float*)(smem + tile * 16384);
    if (kh == 1) {
#pragma unroll
        for (int mt = 0; mt < 4; mt++)
#pragma unroll
            for (int nt = 0; nt < 8; nt++)
                *(float4*)(ep + ((mt * 8 + nt) * 32 + lid) * 4) = *(float4*)acc[mt][nt];
    }
    __syncthreads();
    if (kh == 0) {
        int g = lid >> 2, ti = lid & 3;
#pragma unroll
        for (int mt = 0; mt < 4; mt++) {
            int m0 = mBase + wm * 64 + mt * 16 + g;
#pragma unroll
            for (int nt = 0; nt < 8; nt++) {
                float4 p = *(float4*)(ep + ((mt * 8 + nt) * 32 + lid) * 4);
                int n0 = nBase + wn * 64 + nt * 8 + ti * 2;
                float b0 = bias[n0], b1 = bias[n0 + 1];
                float2 v0 = make_float2(acc[mt][nt][0] + p.x + b0, acc[mt][nt][1] + p.y + b1);
                float2 v1 = make_float2(acc[mt][nt][2] + p.z + b0, acc[mt][nt][3] + p.w + b1);
                *(float2*)(Cc + (size_t)m0 * N + n0) = v0;
                *(float2*)(Cc + (size_t)(m0 + 8) * N + n0) = v1;
            }
        }
    }
}

// ======================= BatchNorm stats -> scale/shift =======================
__global__ void bn_stats(const float* __restrict__ Y, const float* __restrict__ g,
                         const float* __restrict__ b, float* __restrict__ s,
                         float* __restrict__ t) {
    int c0 = blockIdx.x * 32;
    int tid = threadIdx.x;
    int c = tid % 32, r0 = tid / 32;
    float sm = 0.f, s2 = 0.f;
    for (int r = r0; r < M_TOT; r += 8) {
        float v = Y[(size_t)r * FC + c0 + c];
        sm += v; s2 += v * v;
    }
    __shared__ float sh[2][8][32];
    sh[0][r0][c] = sm; sh[1][r0][c] = s2;
    __syncthreads();
    if (r0 == 0) {
        float ts = 0.f, ts2 = 0.f;
#pragma unroll
        for (int i = 0; i < 8; i++) { ts += sh[0][i][c]; ts2 += sh[1][i][c]; }
        float m = ts / (float)M_TOT;
        float var = ts2 / (float)M_TOT - m * m;
        float sc = rsqrtf(var + 1e-5f) * g[c0 + c];
        s[c0 + c] = sc;
        t[c0 + c] = b[c0 + c] - m * sc;
    }
}

__global__ void bn_apply_relu_h4(const float4* __restrict__ Y,
                                 const float* __restrict__ s, const float* __restrict__ t,
                                 __half2* __restrict__ out) {
    int i = blockIdx.x * blockDim.x + threadIdx.x;
    if (i >= M_TOT * FC / 4) return;
    int c = (i * 4) & (FC - 1);
    float4 v = Y[i];
    float a0 = fmaxf(v.x * s[c + 0] + t[c + 0], 0.f);
    float a1 = fmaxf(v.y * s[c + 1] + t[c + 1], 0.f);
    float a2 = fmaxf(v.z * s[c + 2] + t[c + 2], 0.f);
    float a3 = fmaxf(v.w * s[c + 3] + t[c + 3], 0.f);
    out[2 * i]     = __floats2half2_rn(a0, a1);
    out[2 * i + 1] = __floats2half2_rn(a2, a3);
}

// ======================= heads: k-split GEMM with fused BN2 =======================
#define SY_STRIDE 65
#define HEADS_SMEM (128 * SY_STRIDE * 4 + 64 * NP * 4)

__global__ void __launch_bounds__(256) heads_part(const float* __restrict__ Y2) {
    extern __shared__ char hs[];
    float* sY = (float*)hs;
    float* sW = (float*)(hs + 128 * SY_STRIDE * 4);
    int tid = threadIdx.x;
    int m0 = blockIdx.x * 128;
    int ks = blockIdx.y;
    int cg = tid & 15, rt = tid >> 4;

    float acc[8][8];
#pragma unroll
    for (int i = 0; i < 8; i++)
#pragma unroll
        for (int j = 0; j < 8; j++) acc[i][j] = 0.f;

    for (int ch = 0; ch < 2; ch++) {
        int k0 = ks * 128 + ch * 64;
        if (ch) __syncthreads();
#pragma unroll
        for (int i = 0; i < 8; i++) {
            int i4 = tid + i * 256;
            int row = i4 >> 4, c4 = i4 & 15;
            float4 v = *(const float4*)(Y2 + (size_t)(m0 + row) * FC + k0 + c4 * 4);
            int kk = k0 + c4 * 4;
            float* d = sY + row * SY_STRIDE + c4 * 4;
            d[0] = fmaxf(v.x * g_s[kk + 0] + g_t[kk + 0], 0.f);
            d[1] = fmaxf(v.y * g_s[kk + 1] + g_t[kk + 1], 0.f);
            d[2] = fmaxf(v.z * g_s[kk + 2] + g_t[kk + 2], 0.f);
            d[3] = fmaxf(v.w * g_s[kk + 3] + g_t[kk + 3], 0.f);
        }
#pragma unroll
        for (int i = 0; i < 8; i++) {
            int i4 = tid + i * 256;
            int kk = i4 >> 5, c4 = i4 & 31;
            *(float4*)(sW + kk * NP + c4 * 4) =
                *(const float4*)(g_Wcat + (size_t)(k0 + kk) * NP + c4 * 4);
        }
        __syncthreads();

        for (int k = 0; k < 64; k++) {
            float yv[8];
#pragma unroll
            for (int i = 0; i < 8; i++) yv[i] = sY[(rt + 16 * i) * SY_STRIDE + k];
#pragma unroll
            for (int j = 0; j < 4; j++) {
                float2 wv = *(float2*)(sW + k * NP + cg * 2 + 32 * j);
#pragma unroll
                for (int i = 0; i < 8; i++) {
                    acc[i][j * 2]     += yv[i] * wv.x;
                    acc[i][j * 2 + 1] += yv[i] * wv.y;
                }
            }
        }
    }

#pragma unroll
    for (int i = 0; i < 8; i++) {
        int m = m0 + rt + 16 * i;
#pragma unroll
        for (int j = 0; j < 4; j++) {
            *(float2*)&g_hp[ks][m][cg * 2 + 32 * j] =
                make_float2(acc[i][j * 2], acc[i][j * 2 + 1]);
        }
    }
}

__global__ void heads_reduce(float* __restrict__ out) {
    int idx = blockIdx.x * blockDim.x + threadIdx.x;
    if (idx >= M_TOT * OUT_D) return;
    int m = idx / OUT_D, c = idx % OUT_D;
    float a = g_bcat[c];
#pragma unroll
    for (int s = 0; s < 8; s++) a += g_hp[s][m][c];
    out[idx] = a;
}

// ======================= launch =======================
extern "C" void kernel_launch(void* const* d_in, const int* in_sizes, int n_in,
                              void* d_out, int out_size) {
    const float* feat0    = (const float*)d_in[0];
    const float* feat1    = (const float*)d_in[1];
    const float* feat2    = (const float*)d_in[2];
    const float* bbox2d   = (const float*)d_in[3];
    const int*   anchor   = (const int*)  d_in[4];
    const float* fc1_w    = (const float*)d_in[5];
    const float* fc1_b    = (const float*)d_in[6];
    const float* bn1_g    = (const float*)d_in[7];
    const float* bn1_b    = (const float*)d_in[8];
    const float* fc2_w    = (const float*)d_in[9];
    const float* fc2_b    = (const float*)d_in[10];
    const float* bn2_g    = (const float*)d_in[11];
    const float* bn2_b    = (const float*)d_in[12];
    const float* cate_w   = (const float*)d_in[13];
    const float* cate_b   = (const float*)d_in[14];
    const float* bbox3d_w = (const float*)d_in[15];
    const float* bbox3d_b = (const float*)d_in[16];
    const float* yawc_w   = (const float*)d_in[17];
    const float* yawc_b   = (const float*)d_in[18];
    const float* yawr_w   = (const float*)d_in[19];
    const float* yawr_b   = (const float*)d_in[20];
    const float* hgt_w    = (const float*)d_in[21];
    const float* hgt_b    = (const float*)d_in[22];
    float* out = (float*)d_out;

    float *pf0, *pf1, *pf2, *pY1, *pY2, *ps, *pt;
    __half *pXh, *pW1h, *pW2hi, *pW2lo, *pA2h;
    cudaGetSymbolAddress((void**)&pf0, g_f0);
    cudaGetSymbolAddress((void**)&pf1, g_f1);
    cudaGetSymbolAddress((void**)&pf2, g_f2);
    cudaGetSymbolAddress((void**)&pXh, g_Xh);
    cudaGetSymbolAddress((void**)&pW1h, g_W1h);
    cudaGetSymbolAddress((void**)&pW2hi, g_W2hi);
    cudaGetSymbolAddress((void**)&pW2lo, g_W2lo);
    cudaGetSymbolAddress((void**)&pA2h, g_A2h);
    cudaGetSymbolAddress((void**)&pY1, g_Y1);
    cudaGetSymbolAddress((void**)&pY2, g_Y2);
    cudaGetSymbolAddress((void**)&ps, g_s);
    cudaGetSymbolAddress((void**)&pt, g_t);

    cudaFuncSetAttribute(gemm_f16<1>, cudaFuncAttributeMaxDynamicSharedMemorySize,
                         4 * (A_TILE + 1 * B_TILE));
    cudaFuncSetAttribute(gemm_f16<2>, cudaFuncAttributeMaxDynamicSharedMemorySize,
                         4 * (A_TILE + 2 * B_TILE));
    cudaFuncSetAttribute(heads_part, cudaFuncAttributeMaxDynamicSharedMemorySize,
                         HEADS_SMEM);

    cudaStream_t s0 = 0;
    dim3 tpb(32, 8);

    // ---- fork aux streams off the capture stream ----
    cudaEvent_t eFork = e_roiA;   // reuse handles: record fork first
    cudaEventRecord(eFork, s0);
    cudaStreamWaitEvent(s_aux1, eFork, 0);

    // s_aux1: weight prep (independent of roi chain)
    w_to_h4 <<<(K1*FC/4 + 255)/256, 256, 0, s_aux1>>>((const float4*)fc1_w, (__half2*)pW1h, K1*FC/4);
    cudaEventRecord(e_w1, s_aux1);
    split_w4<<<(FC*FC/4 + 255)/256, 256, 0, s_aux1>>>((const float4*)fc2_w, (__half2*)pW2hi, (__half2*)pW2lo, FC*FC/4);
    concat_heads<<<(FC*NP + 255)/256, 256, 0, s_aux1>>>(cate_w, cate_b, bbox3d_w, bbox3d_b,
                                                        yawc_w, yawc_b, yawr_w, yawr_b, hgt_w, hgt_b);
    cudaEventRecord(e_wall, s_aux1);

    // s0: transposes for batches 0,1 then roiA
    transpose_nchw_nhwc<<<dim3(128*128/32, C_CH/32, 2), tpb, 0, s0>>>(feat0, pf0, 128*128);
    transpose_nchw_nhwc<<<dim3(64*64/32,   C_CH/32, 2), tpb, 0, s0>>>(feat1, pf1, 64*64);
    transpose_nchw_nhwc<<<dim3(32*32/32,   C_CH/32, 2), tpb, 0, s0>>>(feat2, pf2, 32*32);
    roi_align_kernel<<<M_TOT/2, C_CH, 0, s0>>>(bbox2d, anchor, 0);
    cudaEventRecord(e_roiA, s0);

    // s_aux2: GEMM1-A (rows 0..1023) once roiA + W1 ready
    cudaStreamWaitEvent(s_aux2, e_roiA, 0);
    cudaStreamWaitEvent(s_aux2, e_w1, 0);
    gemm_f16<1><<<dim3(FC/128, 8), 256, 4*(A_TILE + B_TILE), s_aux2>>>(
        pXh, pW1h, nullptr, fc1_b, pY1, FC, K1, 0);
    cudaEventRecord(e_g1A, s_aux2);

    // s0: transposes for batches 2,3 then roiB, then GEMM1-B
    transpose_nchw_nhwc<<<dim3(128*128/32, C_CH/32, 2), tpb, 0, s0>>>(
        feat0 + (size_t)2*C_CH*128*128, pf0 + (size_t)2*128*128*C_CH, 128*128);
    transpose_nchw_nhwc<<<dim3(64*64/32,   C_CH/32, 2), tpb, 0, s0>>>(
        feat1 + (size_t)2*C_CH*64*64, pf1 + (size_t)2*64*64*C_CH, 64*64);
    transpose_nchw_nhwc<<<dim3(32*32/32,   C_CH/32, 2), tpb, 0, s0>>>(
        feat2 + (size_t)2*C_CH*32*32, pf2 + (size_t)2*32*32*C_CH, 32*32);
    roi_align_kernel<<<M_TOT/2, C_CH, 0, s0>>>(bbox2d, anchor, M_TOT/2);
    cudaStreamWaitEvent(s0, e_w1, 0);
    gemm_f16<1><<<dim3(FC/128, 8), 256, 4*(A_TILE + B_TILE), s0>>>(
        pXh, pW1h, nullptr, fc1_b, pY1, FC, K1, M_TOT/2);

    // join: GEMM1-A + all weight prep back into s0
    cudaStreamWaitEvent(s0, e_g1A, 0);
    cudaStreamWaitEvent(s0, e_wall, 0);

    bn_stats<<<FC/32, 256, 0, s0>>>(pY1, bn1_g, bn1_b, ps, pt);
    bn_apply_relu_h4<<<(M_TOT*FC/4 + 255)/256, 256, 0, s0>>>((const float4*)pY1, ps, pt, (__half2*)pA2h);

    gemm_f16<2><<<dim3(FC/128, M_TOT/128), 256, 4*(A_TILE + 2*B_TILE), s0>>>(
        pA2h, pW2hi, pW2lo, fc2_b, pY2, FC, FC, 0);
    bn_stats<<<FC/32, 256, 0, s0>>>(pY2, bn2_g, bn2_b, ps, pt);

    heads_part<<<dim3(M_TOT/128, 8), 256, HEADS_SMEM, s0>>>(pY2);
    heads_reduce<<<(M_TOT*OUT_D + 255)/256, 256, 0, s0>>>(out);
}

// round 14
// speedup vs baseline: 1.2030x; 1.2030x over previous
#include <cuda_runtime.h>
#include <cuda_fp16.h>
#include <cstdint>
#include <math.h>

#define RES 7
#define SAMP 14
#define C_CH 256
#define B_SZ 4
#define N_ROI 512
#define M_TOT 2048
#define K1 12544
#define FC 1024
#define OUT_D 100
#define NP 128          // padded heads output dim

// ======================= scratch =======================
__device__ __half g_f0[(size_t)B_SZ * 128 * 128 * C_CH];
__device__ __half g_f1[(size_t)B_SZ * 64 * 64 * C_CH];
__device__ __half g_f2[(size_t)B_SZ * 32 * 32 * C_CH];
__device__ __half g_Xh[(size_t)M_TOT * K1];
__device__ __half g_W1h[(size_t)K1 * FC];    // [K][N], single fp16
__device__ __half g_W2hi[(size_t)FC * FC];
__device__ __half g_W2lo[(size_t)FC * FC];
__device__ __half g_A2h[(size_t)M_TOT * FC];
__device__ float g_Y1[(size_t)M_TOT * FC];
__device__ float g_Y2[(size_t)M_TOT * FC];
__device__ float g_bnp[8][2][FC];            // BN partial sums
__device__ float g_s[FC];                    // BN scale
__device__ float g_t[FC];                    // BN shift
__device__ float g_Wcat[(size_t)FC * NP];    // concat heads weights
__device__ float g_bcat[NP];
__device__ float g_hp[8][M_TOT][NP];         // heads k-split partials

// ======================= small PTX helpers =======================
__device__ __forceinline__ uint32_t smem_u32(const void* p) {
    uint32_t a;
    asm("{ .reg .u64 t; cvta.to.shared.u64 t, %1; cvt.u32.u64 %0, t; }" : "=r"(a) : "l"(p));
    return a;
}
__device__ __forceinline__ void cp_async16(uint32_t dst, const void* src) {
    asm volatile("cp.async.cg.shared.global [%0], [%1], 16;" :: "r"(dst), "l"(src));
}
__device__ __forceinline__ void cp_commit() { asm volatile("cp.async.commit_group;"); }
template <int N> __device__ __forceinline__ void cp_wait() {
    asm volatile("cp.async.wait_group %0;" :: "n"(N));
}
__device__ __forceinline__ void ldsm_x4(uint32_t r[4], uint32_t addr) {
    asm volatile("ldmatrix.sync.aligned.m8n8.x4.shared.b16 {%0,%1,%2,%3}, [%4];"
                 : "=r"(r[0]), "=r"(r[1]), "=r"(r[2]), "=r"(r[3]) : "r"(addr));
}
__device__ __forceinline__ void ldsm_x4_t(uint32_t r[4], uint32_t addr) {
    asm volatile("ldmatrix.sync.aligned.m8n8.x4.trans.shared.b16 {%0,%1,%2,%3}, [%4];"
                 : "=r"(r[0]), "=r"(r[1]), "=r"(r[2]), "=r"(r[3]) : "r"(addr));
}
__device__ __forceinline__ void mma16816(float c[4], const uint32_t a[4], const uint32_t b[2]) {
    asm volatile("mma.sync.aligned.m16n8k16.row.col.f32.f16.f16.f32 "
                 "{%0,%1,%2,%3}, {%4,%5,%6,%7}, {%8,%9}, {%0,%1,%2,%3};"
                 : "+f"(c[0]), "+f"(c[1]), "+f"(c[2]), "+f"(c[3])
                 : "r"(a[0]), "r"(a[1]), "r"(a[2]), "r"(a[3]), "r"(b[0]), "r"(b[1]));
}

// ======================= NCHW fp32 -> NHWC fp16 =======================
__global__ void transpose_nchw_nhwc(const float* __restrict__ in,
                                    __half* __restrict__ out, int HW) {
    __shared__ float tile[32][33];
    int b  = blockIdx.z;
    int s0 = blockIdx.x * 32;
    int c0 = blockIdx.y * 32;
    int tx = threadIdx.x, ty = threadIdx.y;
    const float* inb = in + (size_t)b * C_CH * HW;
    __half* outb = out + (size_t)b * HW * C_CH;
#pragma unroll
    for (int i = 0; i < 32; i += 8)
        tile[ty + i][tx] = inb[(size_t)(c0 + ty + i) * HW + s0 + tx];
    __syncthreads();
#pragma unroll
    for (int i = 0; i < 32; i += 8)
        outb[(size_t)(s0 + ty + i) * C_CH + c0 + tx] = __float2half_rn(tile[tx][ty + i]);
}

// ======================= W fp32 -> fp16 (single) =======================
__global__ void w_to_h4(const float4* __restrict__ in, __half2* __restrict__ out, int total4) {
    int i = blockIdx.x * blockDim.x + threadIdx.x;
    if (i >= total4) return;
    float4 v = in[i];
    out[2 * i]     = __floats2half2_rn(v.x, v.y);
    out[2 * i + 1] = __floats2half2_rn(v.z, v.w);
}

// ======================= W fp32 -> hi/lo fp16 =======================
__global__ void split_w4(const float4* __restrict__ in, __half2* __restrict__ hi,
                         __half2* __restrict__ lo, int total4) {
    int i = blockIdx.x * blockDim.x + threadIdx.x;
    if (i >= total4) return;
    float4 v = in[i];
    __half hx = __float2half_rn(v.x), hy = __float2half_rn(v.y);
    __half hz = __float2half_rn(v.z), hw = __float2half_rn(v.w);
    hi[2 * i]     = __halves2half2(hx, hy);
    hi[2 * i + 1] = __halves2half2(hz, hw);
    lo[2 * i]     = __halves2half2(__float2half_rn(v.x - __half2float(hx)),
                                   __float2half_rn(v.y - __half2float(hy)));
    lo[2 * i + 1] = __halves2half2(__float2half_rn(v.z - __half2float(hz)),
                                   __float2half_rn(v.w - __half2float(hw)));
}

// ======================= concat heads weights =======================
__global__ void concat_heads(const float* __restrict__ cw,  const float* __restrict__ cb,
                             const float* __restrict__ bw,  const float* __restrict__ bb_,
                             const float* __restrict__ ycw, const float* __restrict__ ycb,
                             const float* __restrict__ yrw, const float* __restrict__ yrb,
                             const float* __restrict__ hw,  const float* __restrict__ hb) {
    int idx = blockIdx.x * blockDim.x + threadIdx.x;
    if (idx >= FC * NP) return;
    int k = idx >> 7, n = idx & 127;
    float v = 0.f;
    if (n < 4)        v = cw [k * 4  + n];
    else if (n < 22)  v = bw [k * 18 + n - 4];
    else if (n < 58)  v = ycw[k * 36 + n - 22];
    else if (n < 94)  v = yrw[k * 36 + n - 58];
    else if (n < 100) v = hw [k * 6  + n - 94];
    g_Wcat[idx] = v;
    if (k == 0) {
        float bv = 0.f;
        if (n < 4)        bv = cb [n];
        else if (n < 22)  bv = bb_[n - 4];
        else if (n < 58)  bv = ycb[n - 22];
        else if (n < 94)  bv = yrb[n - 58];
        else if (n < 100) bv = hb [n - 94];
        g_bcat[n] = bv;
    }
}

// ======================= ROI align (tap dedup, fp16 feats) -> X fp16 ===========
// 128 threads/block; thread = channel pair via __half2.
__global__ void roi_align_kernel(const float* __restrict__ bbox2d,
                                 const int* __restrict__ anchor) {
    int roi = blockIdx.x;
    int b   = roi / N_ROI;
    int tid = threadIdx.x;   // 0..127

    __shared__ int   ax_p0[2][SAMP], ax_p1[2][SAMP];
    __shared__ float ax_l [2][SAMP], ax_v [2][SAMP];
    __shared__ int   cnt [2][7];
    __shared__ int   toff[2][7][4];   // in half2 units
    __shared__ float twt [2][7][4];

    int level = anchor[roi] / 3;
    float scale = (level == 0) ? 0.25f : (level == 1) ? 0.125f : 0.0625f;
    int   H     = (level == 0) ? 128   : (level == 1) ? 64     : 32;
    const __half* F = (level == 0) ? g_f0 : (level == 1) ? g_f1 : g_f2;
    const __half2* F2 = (const __half2*)(F + (size_t)b * H * H * C_CH);

    if (tid < 2 * SAMP) {
        int axis = tid / SAMP;
        int j    = tid % SAMP;
        float cy = bbox2d[roi*4+0], cx = bbox2d[roi*4+1];
        float hh = bbox2d[roi*4+2], ww = bbox2d[roi*4+3];
        float lo_ = (axis == 0) ? (cy - 0.5f*hh) : (cx - 0.5f*ww);
        float hi_ = (axis == 0) ? (cy + 0.5f*hh) : (cx + 0.5f*ww);
        float start = lo_ * scale - 0.5f;
        float bs    = (hi_ - lo_) * scale / (float)RES;
        float g     = ((float)j + 0.5f) * 0.5f;
        float pos   = start + g * bs;
        float valid = (pos > -1.0f && pos < (float)H) ? 1.0f : 0.0f;
        float p  = fminf(fmaxf(pos, 0.0f), (float)(H - 1));
        int  p0  = (int)floorf(p);
        int  p1  = min(p0 + 1, H - 1);
        ax_p0[axis][j] = p0;  ax_p1[axis][j] = p1;
        ax_l [axis][j] = p - (float)p0;
        ax_v [axis][j] = valid;
    }
    __syncthreads();

    if (tid < 14) {
        int axis = tid / 7, p = tid % 7;
        int pos[4]; float wt[4]; int n = 0;
#pragma unroll
        for (int s = 0; s < 2; s++) {
            int j = 2 * p + s;
            int q0 = ax_p0[axis][j], q1 = ax_p1[axis][j];
            float l = ax_l[axis][j], vv = ax_v[axis][j];
            int   cq[2]  = {q0, q1};
            float cwv[2] = {(1.f - l) * vv, l * vv};
#pragma unroll
            for (int e = 0; e < 2; e++) {
                if (cwv[e] == 0.f) continue;
                bool found = false;
                for (int i = 0; i < n; i++)
                    if (pos[i] == cq[e]) { wt[i] += cwv[e]; found = true; break; }
                if (!found) { pos[n] = cq[e]; wt[n] = cwv[e]; n++; }
            }
        }
        int mult = (axis == 0) ? H * (C_CH / 2) : (C_CH / 2);   // half2 units
        float fac = (axis == 0) ? 0.25f : 1.f;
        cnt[axis][p] = n;
        for (int i = 0; i < n; i++) {
            toff[axis][p][i] = pos[i] * mult;
            twt [axis][p][i] = wt[i] * fac;
        }
    }
    __syncthreads();

    int c2 = tid;   // half2 channel pair
    __half* xrow0 = g_Xh + (size_t)roi * K1 + (size_t)(2 * c2) * 49;
    __half* xrow1 = xrow0 + 49;

#pragma unroll 1
    for (int py = 0; py < 7; py++) {
        int ny = cnt[0][py];
#pragma unroll 1
        for (int px = 0; px < 7; px++) {
            int nx = cnt[1][px];
            float v0 = 0.f, v1 = 0.f;
            for (int iy = 0; iy < ny; iy++) {
                const __half2* Fr = F2 + toff[0][py][iy] + c2;
                float wy = twt[0][py][iy];
                for (int ix = 0; ix < nx; ix++) {
                    float w = wy * twt[1][px][ix];
                    float2 f = __half22float2(Fr[toff[1][px][ix]]);
                    v0 += w * f.x;
                    v1 += w * f.y;
                }
            }
            xrow0[py * 7 + px] = __float2half_rn(v0);
            xrow1[py * 7 + px] = __float2half_rn(v1);
        }
    }
}

// ======================= fp16 HMMA GEMM (NB = #B passes) =======================
#define SA_STRIDE 80               // 32 halves (64B) + 16B pad
#define SB_STRIDE 272              // 128 halves (256B) + 16B pad
#define A_TILE (128 * SA_STRIDE)   // 10240
#define B_TILE (32 * SB_STRIDE)    // 8704

template<int NB>
__global__ void __launch_bounds__(256)
gemm_f16(const __half* __restrict__ A,
         const __half* __restrict__ Whi, const __half* __restrict__ Wlo,
         const float* __restrict__ bias, float* __restrict__ Cc,
         int N, int K) {
    constexpr int STAGE = A_TILE + NB * B_TILE;
    extern __shared__ char smem[];
    uint32_t sb = smem_u32(smem);
    int tid = threadIdx.x, wid = tid >> 5, lid = tid & 31;
    int mBase = blockIdx.y * 128, nBase = blockIdx.x * 128;
    int kh = wid >> 2;
    int wm = (wid >> 1) & 1, wn = wid & 1;

    float acc[4][8][4];
#pragma unroll
    for (int i = 0; i < 4; i++)
#pragma unroll
        for (int j = 0; j < 8; j++)
#pragma unroll
            for (int q = 0; q < 4; q++) acc[i][j][q] = 0.f;

    const int nIter = K >> 5;

    auto load_stage = [&](int iter, int stage) {
        int k0 = iter * 32;
        uint32_t stBase = sb + stage * STAGE;
#pragma unroll
        for (int i = 0; i < 2; i++) {
            int idx = tid + i * 256;
            int row = idx >> 2, ck = idx & 3;
            cp_async16(stBase + row * SA_STRIDE + ck * 16,
                       A + (size_t)(mBase + row) * K + k0 + ck * 8);
        }
#pragma unroll
        for (int i = 0; i < 2 * NB; i++) {
            int idx = tid + i * 256;
            const __half* src = (NB == 2 && idx >= 512) ? Wlo : Whi;
            int within = idx & 511;
            int row = within >> 4, ck = within & 15;
            cp_async16(stBase + A_TILE + (idx >> 9) * B_TILE + row * SB_STRIDE + ck * 16,
                       src + (size_t)(k0 + row) * N + nBase + ck * 8);
        }
        cp_commit();
    };

    load_stage(0, 0);
    if (nIter > 1) load_stage(1, 1);
    if (nIter > 2) load_stage(2, 2);

    for (int it = 0; it < nIter; it++) {
        int stage = it & 3;
        if (it + 3 < nIter) { load_stage(it + 3, (it + 3) & 3); cp_wait<3>(); }
        else if (it + 2 < nIter) cp_wait<2>();
        else if (it + 1 < nIter) cp_wait<1>();
        else cp_wait<0>();
        __syncthreads();

        uint32_t stBase = sb + stage * STAGE;
        uint32_t aB = stBase;
        uint32_t bHiB = stBase + A_TILE, bLoB = bHiB + B_TILE;

        uint32_t ah[4][4], bh[8][2], bl[8][2];
#pragma unroll
        for (int mt = 0; mt < 4; mt++) {
            uint32_t off = (uint32_t)(wm * 64 + mt * 16 + (lid & 15)) * SA_STRIDE
                         + kh * 32 + (lid >> 4) * 16;
            ldsm_x4(ah[mt], aB + off);
        }
#pragma unroll
        for (int np = 0; np < 4; np++) {
            uint32_t off = (uint32_t)(kh * 16 + (lid & 15)) * SB_STRIDE
                         + (wn * 64 + np * 16 + (lid >> 4) * 8) * 2;
            uint32_t t[4];
            ldsm_x4_t(t, bHiB + off);
            bh[np*2][0] = t[0]; bh[np*2][1] = t[1];
            bh[np*2+1][0] = t[2]; bh[np*2+1][1] = t[3];
            if (NB == 2) {
                ldsm_x4_t(t, bLoB + off);
                bl[np*2][0] = t[0]; bl[np*2][1] = t[1];
                bl[np*2+1][0] = t[2]; bl[np*2+1][1] = t[3];
            }
        }
#pragma unroll
        for (int mt = 0; mt < 4; mt++)
#pragma unroll
            for (int nt = 0; nt < 8; nt++) {
                mma16816(acc[mt][nt], ah[mt], bh[nt]);
                if (NB == 2) mma16816(acc[mt][nt], ah[mt], bl[nt]);
            }
        __syncthreads();
    }

    int tile = wm * 2 + wn;
    float* ep = (float*)(smem + tile * 16384);
    if (kh == 1) {
#pragma unroll
        for (int mt = 0; mt < 4; mt++)
#pragma unroll
            for (int nt = 0; nt < 8; nt++)
                *(float4*)(ep + ((mt * 8 + nt) * 32 + lid) * 4) = *(float4*)acc[mt][nt];
    }
    __syncthreads();
    if (kh == 0) {
        int g = lid >> 2, ti = lid & 3;
#pragma unroll
        for (int mt = 0; mt < 4; mt++) {
            int m0 = mBase + wm * 64 + mt * 16 + g;
#pragma unroll
            for (int nt = 0; nt < 8; nt++) {
                float4 p = *(float4*)(ep + ((mt * 8 + nt) * 32 + lid) * 4);
                int n0 = nBase + wn * 64 + nt * 8 + ti * 2;
                float b0 = bias[n0], b1 = bias[n0 + 1];
                float2 v0 = make_float2(acc[mt][nt][0] + p.x + b0, acc[mt][nt][1] + p.y + b1);
                float2 v1 = make_float2(acc[mt][nt][2] + p.z + b0, acc[mt][nt][3] + p.w + b1);
                *(float2*)(Cc + (size_t)m0 * N + n0) = v0;
                *(float2*)(Cc + (size_t)(m0 + 8) * N + n0) = v1;
            }
        }
    }
}

// ======================= BatchNorm: partial stats + finalize =======================
__global__ void bn_stats_part(const float* __restrict__ Y) {
    int c0 = blockIdx.x * 32;
    int seg = blockIdx.y;                 // 8 row segments of 256 rows
    int tid = threadIdx.x;
    int c = tid % 32, r0 = tid / 32;
    float sm = 0.f, s2 = 0.f;
    int rBase = seg * 256;
    for (int r = r0; r < 256; r += 8) {
        float v = Y[(size_t)(rBase + r) * FC + c0 + c];
        sm += v; s2 += v * v;
    }
    __shared__ float sh[2][8][32];
    sh[0][r0][c] = sm; sh[1][r0][c] = s2;
    __syncthreads();
    if (r0 == 0) {
        float ts = 0.f, ts2 = 0.f;
#pragma unroll
        for (int i = 0; i < 8; i++) { ts += sh[0][i][c]; ts2 += sh[1][i][c]; }
        g_bnp[seg][0][c0 + c] = ts;
        g_bnp[seg][1][c0 + c] = ts2;
    }
}

__global__ void bn_finalize(const float* __restrict__ g, const float* __restrict__ b,
                            float* __restrict__ s, float* __restrict__ t) {
    int c = blockIdx.x * blockDim.x + threadIdx.x;
    if (c >= FC) return;
    float ts = 0.f, ts2 = 0.f;
#pragma unroll
    for (int i = 0; i < 8; i++) { ts += g_bnp[i][0][c]; ts2 += g_bnp[i][1][c]; }
    float m = ts / (float)M_TOT;
    float var = ts2 / (float)M_TOT - m * m;
    float sc = rsqrtf(var + 1e-5f) * g[c];
    s[c] = sc;
    t[c] = b[c] - m * sc;
}

__global__ void bn_apply_relu_h4(const float4* __restrict__ Y,
                                 const float* __restrict__ s, const float* __restrict__ t,
                                 __half2* __restrict__ out) {
    int i = blockIdx.x * blockDim.x + threadIdx.x;
    if (i >= M_TOT * FC / 4) return;
    int c = (i * 4) & (FC - 1);
    float4 v = Y[i];
    float a0 = fmaxf(v.x * s[c + 0] + t[c + 0], 0.f);
    float a1 = fmaxf(v.y * s[c + 1] + t[c + 1], 0.f);
    float a2 = fmaxf(v.z * s[c + 2] + t[c + 2], 0.f);
    float a3 = fmaxf(v.w * s[c + 3] + t[c + 3], 0.f);
    out[2 * i]     = __floats2half2_rn(a0, a1);
    out[2 * i + 1] = __floats2half2_rn(a2, a3);
}

// ======================= heads: k-split GEMM with fused BN2 =======================
#define SY_STRIDE 65
#define HEADS_SMEM (128 * SY_STRIDE * 4 + 64 * NP * 4)

__global__ void __launch_bounds__(256) heads_part(const float* __restrict__ Y2) {
    extern __shared__ char hs[];
    float* sY = (float*)hs;
    float* sW = (float*)(hs + 128 * SY_STRIDE * 4);
    int tid = threadIdx.x;
    int m0 = blockIdx.x * 128;
    int ks = blockIdx.y;
    int cg = tid & 15, rt = tid >> 4;

    float acc[8][8];
#pragma unroll
    for (int i = 0; i < 8; i++)
#pragma unroll
        for (int j = 0; j < 8; j++) acc[i][j] = 0.f;

    for (int ch = 0; ch < 2; ch++) {
        int k0 = ks * 128 + ch * 64;
        if (ch) __syncthreads();
#pragma unroll
        for (int i = 0; i < 8; i++) {
            int i4 = tid + i * 256;
            int row = i4 >> 4, c4 = i4 & 15;
            float4 v = *(const float4*)(Y2 + (size_t)(m0 + row) * FC + k0 + c4 * 4);
            int kk = k0 + c4 * 4;
            float* d = sY + row * SY_STRIDE + c4 * 4;
            d[0] = fmaxf(v.x * g_s[kk + 0] + g_t[kk + 0], 0.f);
            d[1] = fmaxf(v.y * g_s[kk + 1] + g_t[kk + 1], 0.f);
            d[2] = fmaxf(v.z * g_s[kk + 2] + g_t[kk + 2], 0.f);
            d[3] = fmaxf(v.w * g_s[kk + 3] + g_t[kk + 3], 0.f);
        }
#pragma unroll
        for (int i = 0; i < 8; i++) {
            int i4 = tid + i * 256;
            int kk = i4 >> 5, c4 = i4 & 31;
            *(float4*)(sW + kk * NP + c4 * 4) =
                *(const float4*)(g_Wcat + (size_t)(k0 + kk) * NP + c4 * 4);
        }
        __syncthreads();

        for (int k = 0; k < 64; k++) {
            float yv[8];
#pragma unroll
            for (int i = 0; i < 8; i++) yv[i] = sY[(rt + 16 * i) * SY_STRIDE + k];
#pragma unroll
            for (int j = 0; j < 4; j++) {
                float2 wv = *(float2*)(sW + k * NP + cg * 2 + 32 * j);
#pragma unroll
                for (int i = 0; i < 8; i++) {
                    acc[i][j * 2]     += yv[i] * wv.x;
                    acc[i][j * 2 + 1] += yv[i] * wv.y;
                }
            }
        }
    }

#pragma unroll
    for (int i = 0; i < 8; i++) {
        int m = m0 + rt + 16 * i;
#pragma unroll
        for (int j = 0; j < 4; j++) {
            *(float2*)&g_hp[ks][m][cg * 2 + 32 * j] =
                make_float2(acc[i][j * 2], acc[i][j * 2 + 1]);
        }
    }
}

__global__ void heads_reduce(float* __restrict__ out) {
    int idx = blockIdx.x * blockDim.x + threadIdx.x;
    if (idx >= M_TOT * OUT_D) return;
    int m = idx / OUT_D, c = idx % OUT_D;
    float a = g_bcat[c];
#pragma unroll
    for (int s = 0; s < 8; s++) a += g_hp[s][m][c];
    out[idx] = a;
}

// ======================= launch =======================
extern "C" void kernel_launch(void* const* d_in, const int* in_sizes, int n_in,
                              void* d_out, int out_size) {
    const float* feat0    = (const float*)d_in[0];
    const float* feat1    = (const float*)d_in[1];
    const float* feat2    = (const float*)d_in[2];
    const float* bbox2d   = (const float*)d_in[3];
    const int*   anchor   = (const int*)  d_in[4];
    const float* fc1_w    = (const float*)d_in[5];
    const float* fc1_b    = (const float*)d_in[6];
    const float* bn1_g    = (const float*)d_in[7];
    const float* bn1_b    = (const float*)d_in[8];
    const float* fc2_w    = (const float*)d_in[9];
    const float* fc2_b    = (const float*)d_in[10];
    const float* bn2_g    = (const float*)d_in[11];
    const float* bn2_b    = (const float*)d_in[12];
    const float* cate_w   = (const float*)d_in[13];
    const float* cate_b   = (const float*)d_in[14];
    const float* bbox3d_w = (const float*)d_in[15];
    const float* bbox3d_b = (const float*)d_in[16];
    const float* yawc_w   = (const float*)d_in[17];
    const float* yawc_b   = (const float*)d_in[18];
    const float* yawr_w   = (const float*)d_in[19];
    const float* yawr_b   = (const float*)d_in[20];
    const float* hgt_w    = (const float*)d_in[21];
    const float* hgt_b    = (const float*)d_in[22];
    float* out = (float*)d_out;

    float *pY1, *pY2, *ps, *pt;
    __half *pf0, *pf1, *pf2, *pXh, *pW1h, *pW2hi, *pW2lo, *pA2h;
    cudaGetSymbolAddress((void**)&pf0, g_f0);
    cudaGetSymbolAddress((void**)&pf1, g_f1);
    cudaGetSymbolAddress((void**)&pf2, g_f2);
    cudaGetSymbolAddress((void**)&pXh, g_Xh);
    cudaGetSymbolAddress((void**)&pW1h, g_W1h);
    cudaGetSymbolAddress((void**)&pW2hi, g_W2hi);
    cudaGetSymbolAddress((void**)&pW2lo, g_W2lo);
    cudaGetSymbolAddress((void**)&pA2h, g_A2h);
    cudaGetSymbolAddress((void**)&pY1, g_Y1);
    cudaGetSymbolAddress((void**)&pY2, g_Y2);
    cudaGetSymbolAddress((void**)&ps, g_s);
    cudaGetSymbolAddress((void**)&pt, g_t);

    cudaFuncSetAttribute(gemm_f16<1>, cudaFuncAttributeMaxDynamicSharedMemorySize,
                         4 * (A_TILE + 1 * B_TILE));
    cudaFuncSetAttribute(gemm_f16<2>, cudaFuncAttributeMaxDynamicSharedMemorySize,
                         4 * (A_TILE + 2 * B_TILE));
    cudaFuncSetAttribute(heads_part, cudaFuncAttributeMaxDynamicSharedMemorySize,
                         HEADS_SMEM);

    dim3 tpb(32, 8);
    transpose_nchw_nhwc<<<dim3(128*128/32, C_CH/32, B_SZ), tpb>>>(feat0, pf0, 128*128);
    transpose_nchw_nhwc<<<dim3(64*64/32,   C_CH/32, B_SZ), tpb>>>(feat1, pf1, 64*64);
    transpose_nchw_nhwc<<<dim3(32*32/32,   C_CH/32, B_SZ), tpb>>>(feat2, pf2, 32*32);

    w_to_h4 <<<(K1*FC/4 + 255)/256, 256>>>((const float4*)fc1_w, (__half2*)pW1h, K1*FC/4);
    split_w4<<<(FC*FC/4 + 255)/256, 256>>>((const float4*)fc2_w, (__half2*)pW2hi, (__half2*)pW2lo, FC*FC/4);
    concat_heads<<<(FC*NP + 255)/256, 256>>>(cate_w, cate_b, bbox3d_w, bbox3d_b,
                                             yawc_w, yawc_b, yawr_w, yawr_b, hgt_w, hgt_b);

    roi_align_kernel<<<M_TOT, 128>>>(bbox2d, anchor);

    // FC1 (K = 12544), single-pass fp16
    gemm_f16<1><<<dim3(FC/128, M_TOT/128), 256, 4*(A_TILE + B_TILE)>>>(
        pXh, pW1h, nullptr, fc1_b, pY1, FC, K1);
    bn_stats_part<<<dim3(FC/32, 8), 256>>>(pY1);
    bn_finalize<<<FC/256, 256>>>(bn1_g, bn1_b, ps, pt);
    bn_apply_relu_h4<<<(M_TOT*FC/4 + 255)/256, 256>>>((const float4*)pY1, ps, pt, (__half2*)pA2h);

    // FC2 (K = 1024), 2-pass (W2 exact split)
    gemm_f16<2><<<dim3(FC/128, M_TOT/128), 256, 4*(A_TILE + 2*B_TILE)>>>(
        pA2h, pW2hi, pW2lo, fc2_b, pY2, FC, FC);
    bn_stats_part<<<dim3(FC/32, 8), 256>>>(pY2);
    bn_finalize<<<FC/256, 256>>>(bn2_g, bn2_b, ps, pt);

    // heads: BN2 fused, k-split partials + reduce
    heads_part<<<dim3(M_TOT/128, 8), 256, HEADS_SMEM>>>(pY2);
    heads_reduce<<<(M_TOT*OUT_D + 255)/256, 256>>>(out);
}

// round 15
// speedup vs baseline: 1.2440x; 1.0340x over previous
#include <cuda_runtime.h>
#include <cuda_fp16.h>
#include <cstdint>
#include <math.h>

#define RES 7
#define SAMP 14
#define C_CH 256
#define B_SZ 4
#define N_ROI 512
#define M_TOT 2048
#define K1 12544
#define FC 1024
#define OUT_D 100
#define NP 128          // padded heads output dim

// ======================= scratch =======================
__device__ __half g_f0[(size_t)B_SZ * 128 * 128 * C_CH];
__device__ __half g_f1[(size_t)B_SZ * 64 * 64 * C_CH];
__device__ __half g_f2[(size_t)B_SZ * 32 * 32 * C_CH];
__device__ __half g_Xh[(size_t)M_TOT * K1];
__device__ __half g_W1h[(size_t)K1 * FC];    // [K][N], single fp16
__device__ __half g_W2h[(size_t)FC * FC];    // [K][N], single fp16
__device__ __half g_A2h[(size_t)M_TOT * FC];
__device__ float g_Y1[(size_t)M_TOT * FC];
__device__ float g_Y2[(size_t)M_TOT * FC];
__device__ float g_bnp[8][2][FC];            // BN partial sums
__device__ float g_s[FC];                    // BN scale
__device__ float g_t[FC];                    // BN shift
__device__ float g_Wcat[(size_t)FC * NP];    // concat heads weights
__device__ float g_bcat[NP];
__device__ float g_hp[8][M_TOT][NP];         // heads k-split partials

// ======================= streams/events (created at load; no device-mem delta) ===
static cudaStream_t s_aux1;
static cudaEvent_t  e_fork, e_wprep;
struct StreamInit {
    StreamInit() {
        cudaStreamCreateWithFlags(&s_aux1, cudaStreamNonBlocking);
        cudaEventCreateWithFlags(&e_fork,  cudaEventDisableTiming);
        cudaEventCreateWithFlags(&e_wprep, cudaEventDisableTiming);
    }
};
static StreamInit s_init;

// ======================= small PTX helpers =======================
__device__ __forceinline__ uint32_t smem_u32(const void* p) {
    uint32_t a;
    asm("{ .reg .u64 t; cvta.to.shared.u64 t, %1; cvt.u32.u64 %0, t; }" : "=r"(a) : "l"(p));
    return a;
}
__device__ __forceinline__ void cp_async16(uint32_t dst, const void* src) {
    asm volatile("cp.async.cg.shared.global [%0], [%1], 16;" :: "r"(dst), "l"(src));
}
__device__ __forceinline__ void cp_commit() { asm volatile("cp.async.commit_group;"); }
template <int N> __device__ __forceinline__ void cp_wait() {
    asm volatile("cp.async.wait_group %0;" :: "n"(N));
}
__device__ __forceinline__ void ldsm_x4(uint32_t r[4], uint32_t addr) {
    asm volatile("ldmatrix.sync.aligned.m8n8.x4.shared.b16 {%0,%1,%2,%3}, [%4];"
                 : "=r"(r[0]), "=r"(r[1]), "=r"(r[2]), "=r"(r[3]) : "r"(addr));
}
__device__ __forceinline__ void ldsm_x4_t(uint32_t r[4], uint32_t addr) {
    asm volatile("ldmatrix.sync.aligned.m8n8.x4.trans.shared.b16 {%0,%1,%2,%3}, [%4];"
                 : "=r"(r[0]), "=r"(r[1]), "=r"(r[2]), "=r"(r[3]) : "r"(addr));
}
__device__ __forceinline__ void mma16816(float c[4], const uint32_t a[4], const uint32_t b[2]) {
    asm volatile("mma.sync.aligned.m16n8k16.row.col.f32.f16.f16.f32 "
                 "{%0,%1,%2,%3}, {%4,%5,%6,%7}, {%8,%9}, {%0,%1,%2,%3};"
                 : "+f"(c[0]), "+f"(c[1]), "+f"(c[2]), "+f"(c[3])
                 : "r"(a[0]), "r"(a[1]), "r"(a[2]), "r"(a[3]), "r"(b[0]), "r"(b[1]));
}

// ======================= NCHW fp32 -> NHWC fp16 =======================
__global__ void transpose_nchw_nhwc(const float* __restrict__ in,
                                    __half* __restrict__ out, int HW) {
    __shared__ float tile[32][33];
    int b  = blockIdx.z;
    int s0 = blockIdx.x * 32;
    int c0 = blockIdx.y * 32;
    int tx = threadIdx.x, ty = threadIdx.y;
    const float* inb = in + (size_t)b * C_CH * HW;
    __half* outb = out + (size_t)b * HW * C_CH;
#pragma unroll
    for (int i = 0; i < 32; i += 8)
        tile[ty + i][tx] = inb[(size_t)(c0 + ty + i) * HW + s0 + tx];
    __syncthreads();
#pragma unroll
    for (int i = 0; i < 32; i += 8)
        outb[(size_t)(s0 + ty + i) * C_CH + c0 + tx] = __float2half_rn(tile[tx][ty + i]);
}

// ======================= W fp32 -> fp16 (single) =======================
__global__ void w_to_h4(const float4* __restrict__ in, __half2* __restrict__ out, int total4) {
    int i = blockIdx.x * blockDim.x + threadIdx.x;
    if (i >= total4) return;
    float4 v = in[i];
    out[2 * i]     = __floats2half2_rn(v.x, v.y);
    out[2 * i + 1] = __floats2half2_rn(v.z, v.w);
}

// ======================= concat heads weights =======================
__global__ void concat_heads(const float* __restrict__ cw,  const float* __restrict__ cb,
                             const float* __restrict__ bw,  const float* __restrict__ bb_,
                             const float* __restrict__ ycw, const float* __restrict__ ycb,
                             const float* __restrict__ yrw, const float* __restrict__ yrb,
                             const float* __restrict__ hw,  const float* __restrict__ hb) {
    int idx = blockIdx.x * blockDim.x + threadIdx.x;
    if (idx >= FC * NP) return;
    int k = idx >> 7, n = idx & 127;
    float v = 0.f;
    if (n < 4)        v = cw [k * 4  + n];
    else if (n < 22)  v = bw [k * 18 + n - 4];
    else if (n < 58)  v = ycw[k * 36 + n - 22];
    else if (n < 94)  v = yrw[k * 36 + n - 58];
    else if (n < 100) v = hw [k * 6  + n - 94];
    g_Wcat[idx] = v;
    if (k == 0) {
        float bv = 0.f;
        if (n < 4)        bv = cb [n];
        else if (n < 22)  bv = bb_[n - 4];
        else if (n < 58)  bv = ycb[n - 22];
        else if (n < 94)  bv = yrb[n - 58];
        else if (n < 100) bv = hb [n - 94];
        g_bcat[n] = bv;
    }
}

// ======================= ROI align (tap dedup, fp16 feats) -> X fp16 ===========
// 128 threads/block; thread = channel pair via __half2.
__global__ void roi_align_kernel(const float* __restrict__ bbox2d,
                                 const int* __restrict__ anchor) {
    int roi = blockIdx.x;
    int b   = roi / N_ROI;
    int tid = threadIdx.x;   // 0..127

    __shared__ int   ax_p0[2][SAMP], ax_p1[2][SAMP];
    __shared__ float ax_l [2][SAMP], ax_v [2][SAMP];
    __shared__ int   cnt [2][7];
    __shared__ int   toff[2][7][4];   // in half2 units
    __shared__ float twt [2][7][4];

    int level = anchor[roi] / 3;
    float scale = (level == 0) ? 0.25f : (level == 1) ? 0.125f : 0.0625f;
    int   H     = (level == 0) ? 128   : (level == 1) ? 64     : 32;
    const __half* F = (level == 0) ? g_f0 : (level == 1) ? g_f1 : g_f2;
    const __half2* F2 = (const __half2*)(F + (size_t)b * H * H * C_CH);

    if (tid < 2 * SAMP) {
        int axis = tid / SAMP;
        int j    = tid % SAMP;
        float cy = bbox2d[roi*4+0], cx = bbox2d[roi*4+1];
        float hh = bbox2d[roi*4+2], ww = bbox2d[roi*4+3];
        float lo_ = (axis == 0) ? (cy - 0.5f*hh) : (cx - 0.5f*ww);
        float hi_ = (axis == 0) ? (cy + 0.5f*hh) : (cx + 0.5f*ww);
        float start = lo_ * scale - 0.5f;
        float bs    = (hi_ - lo_) * scale / (float)RES;
        float g     = ((float)j + 0.5f) * 0.5f;
        float pos   = start + g * bs;
        float valid = (pos > -1.0f && pos < (float)H) ? 1.0f : 0.0f;
        float p  = fminf(fmaxf(pos, 0.0f), (float)(H - 1));
        int  p0  = (int)floorf(p);
        int  p1  = min(p0 + 1, H - 1);
        ax_p0[axis][j] = p0;  ax_p1[axis][j] = p1;
        ax_l [axis][j] = p - (float)p0;
        ax_v [axis][j] = valid;
    }
    __syncthreads();

    if (tid < 14) {
        int axis = tid / 7, p = tid % 7;
        int pos[4]; float wt[4]; int n = 0;
#pragma unroll
        for (int s = 0; s < 2; s++) {
            int j = 2 * p + s;
            int q0 = ax_p0[axis][j], q1 = ax_p1[axis][j];
            float l = ax_l[axis][j], vv = ax_v[axis][j];
            int   cq[2]  = {q0, q1};
            float cwv[2] = {(1.f - l) * vv, l * vv};
#pragma unroll
            for (int e = 0; e < 2; e++) {
                if (cwv[e] == 0.f) continue;
                bool found = false;
                for (int i = 0; i < n; i++)
                    if (pos[i] == cq[e]) { wt[i] += cwv[e]; found = true; break; }
                if (!found) { pos[n] = cq[e]; wt[n] = cwv[e]; n++; }
            }
        }
        int mult = (axis == 0) ? H * (C_CH / 2) : (C_CH / 2);   // half2 units
        float fac = (axis == 0) ? 0.25f : 1.f;
        cnt[axis][p] = n;
        for (int i = 0; i < n; i++) {
            toff[axis][p][i] = pos[i] * mult;
            twt [axis][p][i] = wt[i] * fac;
        }
    }
    __syncthreads();

    int c2 = tid;   // half2 channel pair
    __half* xrow0 = g_Xh + (size_t)roi * K1 + (size_t)(2 * c2) * 49;
    __half* xrow1 = xrow0 + 49;

#pragma unroll 1
    for (int py = 0; py < 7; py++) {
        int ny = cnt[0][py];
#pragma unroll 1
        for (int px = 0; px < 7; px++) {
            int nx = cnt[1][px];
            float v0 = 0.f, v1 = 0.f;
            for (int iy = 0; iy < ny; iy++) {
                const __half2* Fr = F2 + toff[0][py][iy] + c2;
                float wy = twt[0][py][iy];
                for (int ix = 0; ix < nx; ix++) {
                    float w = wy * twt[1][px][ix];
                    float2 f = __half22float2(Fr[toff[1][px][ix]]);
                    v0 += w * f.x;
                    v1 += w * f.y;
                }
            }
            xrow0[py * 7 + px] = __float2half_rn(v0);
            xrow1[py * 7 + px] = __float2half_rn(v1);
        }
    }
}

// ======================= fp16 HMMA GEMM (single-pass) =======================
#define SA_STRIDE 80               // 32 halves (64B) + 16B pad
#define SB_STRIDE 272              // 128 halves (256B) + 16B pad
#define A_TILE (128 * SA_STRIDE)   // 10240
#define B_TILE (32 * SB_STRIDE)    // 8704
#define STAGE_B (A_TILE + B_TILE)  // 18944
#define GEMM_SMEM (4 * STAGE_B)    // 75776

__global__ void __launch_bounds__(256)
gemm_f16(const __half* __restrict__ A, const __half* __restrict__ W,
         const float* __restrict__ bias, float* __restrict__ Cc,
         int N, int K) {
    extern __shared__ char smem[];
    uint32_t sb = smem_u32(smem);
    int tid = threadIdx.x, wid = tid >> 5, lid = tid & 31;
    int mBase = blockIdx.y * 128, nBase = blockIdx.x * 128;
    int kh = wid >> 2;
    int wm = (wid >> 1) & 1, wn = wid & 1;

    float acc[4][8][4];
#pragma unroll
    for (int i = 0; i < 4; i++)
#pragma unroll
        for (int j = 0; j < 8; j++)
#pragma unroll
            for (int q = 0; q < 4; q++) acc[i][j][q] = 0.f;

    const int nIter = K >> 5;

    auto load_stage = [&](int iter, int stage) {
        int k0 = iter * 32;
        uint32_t stBase = sb + stage * STAGE_B;
#pragma unroll
        for (int i = 0; i < 2; i++) {
            int idx = tid + i * 256;
            int row = idx >> 2, ck = idx & 3;
            cp_async16(stBase + row * SA_STRIDE + ck * 16,
                       A + (size_t)(mBase + row) * K + k0 + ck * 8);
        }
#pragma unroll
        for (int i = 0; i < 2; i++) {
            int idx = tid + i * 256;
            int row = idx >> 4, ck = idx & 15;
            cp_async16(stBase + A_TILE + row * SB_STRIDE + ck * 16,
                       W + (size_t)(k0 + row) * N + nBase + ck * 8);
        }
        cp_commit();
    };

    load_stage(0, 0);
    if (nIter > 1) load_stage(1, 1);
    if (nIter > 2) load_stage(2, 2);

    for (int it = 0; it < nIter; it++) {
        int stage = it & 3;
        if (it + 3 < nIter) { load_stage(it + 3, (it + 3) & 3); cp_wait<3>(); }
        else if (it + 2 < nIter) cp_wait<2>();
        else if (it + 1 < nIter) cp_wait<1>();
        else cp_wait<0>();
        __syncthreads();

        uint32_t stBase = sb + stage * STAGE_B;
        uint32_t aB = stBase;
        uint32_t bB = stBase + A_TILE;

        uint32_t ah[4][4], bh[8][2];
#pragma unroll
        for (int mt = 0; mt < 4; mt++) {
            uint32_t off = (uint32_t)(wm * 64 + mt * 16 + (lid & 15)) * SA_STRIDE
                         + kh * 32 + (lid >> 4) * 16;
            ldsm_x4(ah[mt], aB + off);
        }
#pragma unroll
        for (int np = 0; np < 4; np++) {
            uint32_t off = (uint32_t)(kh * 16 + (lid & 15)) * SB_STRIDE
                         + (wn * 64 + np * 16 + (lid >> 4) * 8) * 2;
            uint32_t t[4];
            ldsm_x4_t(t, bB + off);
            bh[np*2][0] = t[0]; bh[np*2][1] = t[1];
            bh[np*2+1][0] = t[2]; bh[np*2+1][1] = t[3];
        }
#pragma unroll
        for (int mt = 0; mt < 4; mt++)
#pragma unroll
            for (int nt = 0; nt < 8; nt++)
                mma16816(acc[mt][nt], ah[mt], bh[nt]);
        __syncthreads();
    }

    int tile = wm * 2 + wn;
    float* ep = (float*)(smem + tile * 16384);
    if (kh == 1) {
#pragma unroll
        for (int mt = 0; mt < 4; mt++)
#pragma unroll
            for (int nt = 0; nt < 8; nt++)
                *(float4*)(ep + ((mt * 8 + nt) * 32 + lid) * 4) = *(float4*)acc[mt][nt];
    }
    __syncthreads();
    if (kh == 0) {
        int g = lid >> 2, ti = lid & 3;
#pragma unroll
        for (int mt = 0; mt < 4; mt++) {
            int m0 = mBase + wm * 64 + mt * 16 + g;
#pragma unroll
            for (int nt = 0; nt < 8; nt++) {
                float4 p = *(float4*)(ep + ((mt * 8 + nt) * 32 + lid) * 4);
                int n0 = nBase + wn * 64 + nt * 8 + ti * 2;
                float b0 = bias[n0], b1 = bias[n0 + 1];
                float2 v0 = make_float2(acc[mt][nt][0] + p.x + b0, acc[mt][nt][1] + p.y + b1);
                float2 v1 = make_float2(acc[mt][nt][2] + p.z + b0, acc[mt][nt][3] + p.w + b1);
                *(float2*)(Cc + (size_t)m0 * N + n0) = v0;
                *(float2*)(Cc + (size_t)(m0 + 8) * N + n0) = v1;
            }
        }
    }
}

// ======================= BatchNorm: partial stats + finalize =======================
__global__ void bn_stats_part(const float* __restrict__ Y) {
    int c0 = blockIdx.x * 32;
    int seg = blockIdx.y;                 // 8 row segments of 256 rows
    int tid = threadIdx.x;
    int c = tid % 32, r0 = tid / 32;
    float sm = 0.f, s2 = 0.f;
    int rBase = seg * 256;
    for (int r = r0; r < 256; r += 8) {
        float v = Y[(size_t)(rBase + r) * FC + c0 + c];
        sm += v; s2 += v * v;
    }
    __shared__ float sh[2][8][32];
    sh[0][r0][c] = sm; sh[1][r0][c] = s2;
    __syncthreads();
    if (r0 == 0) {
        float ts = 0.f, ts2 = 0.f;
#pragma unroll
        for (int i = 0; i < 8; i++) { ts += sh[0][i][c]; ts2 += sh[1][i][c]; }
        g_bnp[seg][0][c0 + c] = ts;
        g_bnp[seg][1][c0 + c] = ts2;
    }
}

__global__ void bn_finalize(const float* __restrict__ g, const float* __restrict__ b,
                            float* __restrict__ s, float* __restrict__ t) {
    int c = blockIdx.x * blockDim.x + threadIdx.x;
    if (c >= FC) return;
    float ts = 0.f, ts2 = 0.f;
#pragma unroll
    for (int i = 0; i < 8; i++) { ts += g_bnp[i][0][c]; ts2 += g_bnp[i][1][c]; }
    float m = ts / (float)M_TOT;
    float var = ts2 / (float)M_TOT - m * m;
    float sc = rsqrtf(var + 1e-5f) * g[c];
    s[c] = sc;
    t[c] = b[c] - m * sc;
}

__global__ void bn_apply_relu_h4(const float4* __restrict__ Y,
                                 const float* __restrict__ s, const float* __restrict__ t,
                                 __half2* __restrict__ out) {
    int i = blockIdx.x * blockDim.x + threadIdx.x;
    if (i >= M_TOT * FC / 4) return;
    int c = (i * 4) & (FC - 1);
    float4 v = Y[i];
    float a0 = fmaxf(v.x * s[c + 0] + t[c + 0], 0.f);
    float a1 = fmaxf(v.y * s[c + 1] + t[c + 1], 0.f);
    float a2 = fmaxf(v.z * s[c + 2] + t[c + 2], 0.f);
    float a3 = fmaxf(v.w * s[c + 3] + t[c + 3], 0.f);
    out[2 * i]     = __floats2half2_rn(a0, a1);
    out[2 * i + 1] = __floats2half2_rn(a2, a3);
}

// ======================= heads: k-split GEMM with fused BN2 =======================
#define SY_STRIDE 65
#define HEADS_SMEM (128 * SY_STRIDE * 4 + 64 * NP * 4)

__global__ void __launch_bounds__(256) heads_part(const float* __restrict__ Y2) {
    extern __shared__ char hs[];
    float* sY = (float*)hs;
    float* sW = (float*)(hs + 128 * SY_STRIDE * 4);
    int tid = threadIdx.x;
    int m0 = blockIdx.x * 128;
    int ks = blockIdx.y;
    int cg = tid & 15, rt = tid >> 4;

    float acc[8][8];
#pragma unroll
    for (int i = 0; i < 8; i++)
#pragma unroll
        for (int j = 0; j < 8; j++) acc[i][j] = 0.f;

    for (int ch = 0; ch < 2; ch++) {
        int k0 = ks * 128 + ch * 64;
        if (ch) __syncthreads();
#pragma unroll
        for (int i = 0; i < 8; i++) {
            int i4 = tid + i * 256;
            int row = i4 >> 4, c4 = i4 & 15;
            float4 v = *(const float4*)(Y2 + (size_t)(m0 + row) * FC + k0 + c4 * 4);
            int kk = k0 + c4 * 4;
            float* d = sY + row * SY_STRIDE + c4 * 4;
            d[0] = fmaxf(v.x * g_s[kk + 0] + g_t[kk + 0], 0.f);
            d[1] = fmaxf(v.y * g_s[kk + 1] + g_t[kk + 1], 0.f);
            d[2] = fmaxf(v.z * g_s[kk + 2] + g_t[kk + 2], 0.f);
            d[3] = fmaxf(v.w * g_s[kk + 3] + g_t[kk + 3], 0.f);
        }
#pragma unroll
        for (int i = 0; i < 8; i++) {
            int i4 = tid + i * 256;
            int kk = i4 >> 5, c4 = i4 & 31;
            *(float4*)(sW + kk * NP + c4 * 4) =
                *(const float4*)(g_Wcat + (size_t)(k0 + kk) * NP + c4 * 4);
        }
        __syncthreads();

        for (int k = 0; k < 64; k++) {
            float yv[8];
#pragma unroll
            for (int i = 0; i < 8; i++) yv[i] = sY[(rt + 16 * i) * SY_STRIDE + k];
#pragma unroll
            for (int j = 0; j < 4; j++) {
                float2 wv = *(float2*)(sW + k * NP + cg * 2 + 32 * j);
#pragma unroll
                for (int i = 0; i < 8; i++) {
                    acc[i][j * 2]     += yv[i] * wv.x;
                    acc[i][j * 2 + 1] += yv[i] * wv.y;
                }
            }
        }
    }

#pragma unroll
    for (int i = 0; i < 8; i++) {
        int m = m0 + rt + 16 * i;
#pragma unroll
        for (int j = 0; j < 4; j++) {
            *(float2*)&g_hp[ks][m][cg * 2 + 32 * j] =
                make_float2(acc[i][j * 2], acc[i][j * 2 + 1]);
        }
    }
}

__global__ void heads_reduce(float* __restrict__ out) {
    int idx = blockIdx.x * blockDim.x + threadIdx.x;
    if (idx >= M_TOT * OUT_D) return;
    int m = idx / OUT_D, c = idx % OUT_D;
    float a = g_bcat[c];
#pragma unroll
    for (int s = 0; s < 8; s++) a += g_hp[s][m][c];
    out[idx] = a;
}

// ======================= launch =======================
extern "C" void kernel_launch(void* const* d_in, const int* in_sizes, int n_in,
                              void* d_out, int out_size) {
    const float* feat0    = (const float*)d_in[0];
    const float* feat1    = (const float*)d_in[1];
    const float* feat2    = (const float*)d_in[2];
    const float* bbox2d   = (const float*)d_in[3];
    const int*   anchor   = (const int*)  d_in[4];
    const float* fc1_w    = (const float*)d_in[5];
    const float* fc1_b    = (const float*)d_in[6];
    const float* bn1_g    = (const float*)d_in[7];
    const float* bn1_b    = (const float*)d_in[8];
    const float* fc2_w    = (const float*)d_in[9];
    const float* fc2_b    = (const float*)d_in[10];
    const float* bn2_g    = (const float*)d_in[11];
    const float* bn2_b    = (const float*)d_in[12];
    const float* cate_w   = (const float*)d_in[13];
    const float* cate_b   = (const float*)d_in[14];
    const float* bbox3d_w = (const float*)d_in[15];
    const float* bbox3d_b = (const float*)d_in[16];
    const float* yawc_w   = (const float*)d_in[17];
    const float* yawc_b   = (const float*)d_in[18];
    const float* yawr_w   = (const float*)d_in[19];
    const float* yawr_b   = (const float*)d_in[20];
    const float* hgt_w    = (const float*)d_in[21];
    const float* hgt_b    = (const float*)d_in[22];
    float* out = (float*)d_out;

    float *pY1, *pY2, *ps, *pt;
    __half *pf0, *pf1, *pf2, *pXh, *pW1h, *pW2h, *pA2h;
    cudaGetSymbolAddress((void**)&pf0, g_f0);
    cudaGetSymbolAddress((void**)&pf1, g_f1);
    cudaGetSymbolAddress((void**)&pf2, g_f2);
    cudaGetSymbolAddress((void**)&pXh, g_Xh);
    cudaGetSymbolAddress((void**)&pW1h, g_W1h);
    cudaGetSymbolAddress((void**)&pW2h, g_W2h);
    cudaGetSymbolAddress((void**)&pA2h, g_A2h);
    cudaGetSymbolAddress((void**)&pY1, g_Y1);
    cudaGetSymbolAddress((void**)&pY2, g_Y2);
    cudaGetSymbolAddress((void**)&ps, g_s);
    cudaGetSymbolAddress((void**)&pt, g_t);

    cudaFuncSetAttribute(gemm_f16, cudaFuncAttributeMaxDynamicSharedMemorySize, GEMM_SMEM);
    cudaFuncSetAttribute(heads_part, cudaFuncAttributeMaxDynamicSharedMemorySize, HEADS_SMEM);

    cudaStream_t s0 = 0;
    dim3 tpb(32, 8);

    // fork: weight prep on aux stream, hidden under transpose+roi
    cudaEventRecord(e_fork, s0);
    cudaStreamWaitEvent(s_aux1, e_fork, 0);
    w_to_h4<<<(K1*FC/4 + 255)/256, 256, 0, s_aux1>>>((const float4*)fc1_w, (__half2*)pW1h, K1*FC/4);
    w_to_h4<<<(FC*FC/4 + 255)/256, 256, 0, s_aux1>>>((const float4*)fc2_w, (__half2*)pW2h, FC*FC/4);
    concat_heads<<<(FC*NP + 255)/256, 256, 0, s_aux1>>>(cate_w, cate_b, bbox3d_w, bbox3d_b,
                                                        yawc_w, yawc_b, yawr_w, yawr_b, hgt_w, hgt_b);
    cudaEventRecord(e_wprep, s_aux1);

    // main chain
    transpose_nchw_nhwc<<<dim3(128*128/32, C_CH/32, B_SZ), tpb, 0, s0>>>(feat0, pf0, 128*128);
    transpose_nchw_nhwc<<<dim3(64*64/32,   C_CH/32, B_SZ), tpb, 0, s0>>>(feat1, pf1, 64*64);
    transpose_nchw_nhwc<<<dim3(32*32/32,   C_CH/32, B_SZ), tpb, 0, s0>>>(feat2, pf2, 32*32);

    roi_align_kernel<<<M_TOT, 128, 0, s0>>>(bbox2d, anchor);

    cudaStreamWaitEvent(s0, e_wprep, 0);   // join weight prep

    // FC1 (K = 12544), single-pass fp16
    gemm_f16<<<dim3(FC/128, M_TOT/128), 256, GEMM_SMEM, s0>>>(pXh, pW1h, fc1_b, pY1, FC, K1);
    bn_stats_part<<<dim3(FC/32, 8), 256, 0, s0>>>(pY1);
    bn_finalize<<<FC/256, 256, 0, s0>>>(bn1_g, bn1_b, ps, pt);
    bn_apply_relu_h4<<<(M_TOT*FC/4 + 255)/256, 256, 0, s0>>>((const float4*)pY1, ps, pt, (__half2*)pA2h);

    // FC2 (K = 1024), single-pass fp16
    gemm_f16<<<dim3(FC/128, M_TOT/128), 256, GEMM_SMEM, s0>>>(pA2h, pW2h, fc2_b, pY2, FC, FC);
    bn_stats_part<<<dim3(FC/32, 8), 256, 0, s0>>>(pY2);
    bn_finalize<<<FC/256, 256, 0, s0>>>(bn2_g, bn2_b, ps, pt);

    // heads: BN2 fused, k-split partials + reduce
    heads_part<<<dim3(M_TOT/128, 8), 256, HEADS_SMEM, s0>>>(pY2);
    heads_reduce<<<(M_TOT*OUT_D + 255)/256, 256, 0, s0>>>(out);
}

// round 16
// speedup vs baseline: 1.7724x; 1.4248x over previous
#include <cuda_runtime.h>
#include <cuda_fp16.h>
#include <cstdint>
#include <math.h>

#define RES 7
#define SAMP 14
#define C_CH 256
#define B_SZ 4
#define N_ROI 512
#define M_TOT 2048
#define K1 12544
#define FC 1024
#define OUT_D 100
#define NP 128          // padded heads output dim

// ======================= scratch =======================
__device__ __half g_f0[(size_t)B_SZ * 128 * 128 * C_CH];
__device__ __half g_f1[(size_t)B_SZ * 64 * 64 * C_CH];
__device__ __half g_f2[(size_t)B_SZ * 32 * 32 * C_CH];
__device__ __half g_Xh[(size_t)M_TOT * K1];     // [roi][pix][c] pixel-major
__device__ __half g_W1h[(size_t)K1 * FC];       // [k'=pix*256+c][N] (permuted)
__device__ __half g_W2h[(size_t)FC * FC];
__device__ __half g_A2h[(size_t)M_TOT * FC];
__device__ __half g_Y1h[(size_t)M_TOT * FC];    // FC1 out, fp16
__device__ float g_Y2[(size_t)M_TOT * FC];
__device__ float g_bnp[8][2][FC];               // BN partial sums
__device__ float g_s[FC];                       // BN scale
__device__ float g_t[FC];                       // BN shift
__device__ float g_Wcat[(size_t)FC * NP];       // concat heads weights
__device__ float g_bcat[NP];
__device__ float g_hp[8][M_TOT][NP];            // heads k-split partials

// ======================= streams/events =======================
static cudaStream_t s_aux1;
static cudaEvent_t  e_fork, e_wprep;
struct StreamInit {
    StreamInit() {
        cudaStreamCreateWithFlags(&s_aux1, cudaStreamNonBlocking);
        cudaEventCreateWithFlags(&e_fork,  cudaEventDisableTiming);
        cudaEventCreateWithFlags(&e_wprep, cudaEventDisableTiming);
    }
};
static StreamInit s_init;

// ======================= small PTX helpers =======================
__device__ __forceinline__ uint32_t smem_u32(const void* p) {
    uint32_t a;
    asm("{ .reg .u64 t; cvta.to.shared.u64 t, %1; cvt.u32.u64 %0, t; }" : "=r"(a) : "l"(p));
    return a;
}
__device__ __forceinline__ void cp_async16(uint32_t dst, const void* src) {
    asm volatile("cp.async.cg.shared.global [%0], [%1], 16;" :: "r"(dst), "l"(src));
}
__device__ __forceinline__ void cp_commit() { asm volatile("cp.async.commit_group;"); }
template <int N> __device__ __forceinline__ void cp_wait() {
    asm volatile("cp.async.wait_group %0;" :: "n"(N));
}
__device__ __forceinline__ void ldsm_x4(uint32_t r[4], uint32_t addr) {
    asm volatile("ldmatrix.sync.aligned.m8n8.x4.shared.b16 {%0,%1,%2,%3}, [%4];"
                 : "=r"(r[0]), "=r"(r[1]), "=r"(r[2]), "=r"(r[3]) : "r"(addr));
}
__device__ __forceinline__ void ldsm_x4_t(uint32_t r[4], uint32_t addr) {
    asm volatile("ldmatrix.sync.aligned.m8n8.x4.trans.shared.b16 {%0,%1,%2,%3}, [%4];"
                 : "=r"(r[0]), "=r"(r[1]), "=r"(r[2]), "=r"(r[3]) : "r"(addr));
}
__device__ __forceinline__ void mma16816(float c[4], const uint32_t a[4], const uint32_t b[2]) {
    asm volatile("mma.sync.aligned.m16n8k16.row.col.f32.f16.f16.f32 "
                 "{%0,%1,%2,%3}, {%4,%5,%6,%7}, {%8,%9}, {%0,%1,%2,%3};"
                 : "+f"(c[0]), "+f"(c[1]), "+f"(c[2]), "+f"(c[3])
                 : "r"(a[0]), "r"(a[1]), "r"(a[2]), "r"(a[3]), "r"(b[0]), "r"(b[1]));
}

// ======================= merged NCHW fp32 -> NHWC fp16 =======================
__global__ void transpose_all(const float* __restrict__ f0, const float* __restrict__ f1,
                              const float* __restrict__ f2) {
    __shared__ float tile[32][33];
    int bx = blockIdx.x;
    const float* in; __half* out; int HW;
    if (bx < 512)      { in = f0; out = g_f0; HW = 128 * 128; }
    else if (bx < 640) { in = f1; out = g_f1; HW = 64 * 64;  bx -= 512; }
    else               { in = f2; out = g_f2; HW = 32 * 32;  bx -= 640; }
    int b  = blockIdx.z;
    int s0 = bx * 32;
    int c0 = blockIdx.y * 32;
    int tx = threadIdx.x, ty = threadIdx.y;
    const float* inb = in + (size_t)b * C_CH * HW;
    __half* outb = out + (size_t)b * HW * C_CH;
#pragma unroll
    for (int i = 0; i < 32; i += 8)
        tile[ty + i][tx] = inb[(size_t)(c0 + ty + i) * HW + s0 + tx];
    __syncthreads();
#pragma unroll
    for (int i = 0; i < 32; i += 8)
        outb[(size_t)(s0 + ty + i) * C_CH + c0 + tx] = __float2half_rn(tile[tx][ty + i]);
}

// ======================= W1: fp32 [c*49+pix][N] -> fp16 [pix*256+c][N] ==========
__global__ void w1_perm_h(const float4* __restrict__ in, __half2* __restrict__ out) {
    int tid = threadIdx.x;              // 0..255 (float4 within row)
    int kp  = blockIdx.x;               // output row 0..12543
    int pix = kp >> 8, c = kp & 255;
    int kin = c * 49 + pix;
    float4 v = in[(size_t)kin * 256 + tid];
    out[(size_t)kp * 512 + 2 * tid]     = __floats2half2_rn(v.x, v.y);
    out[(size_t)kp * 512 + 2 * tid + 1] = __floats2half2_rn(v.z, v.w);
}

// ======================= W2 fp32 -> fp16 =======================
__global__ void w_to_h4(const float4* __restrict__ in, __half2* __restrict__ out, int total4) {
    int i = blockIdx.x * blockDim.x + threadIdx.x;
    if (i >= total4) return;
    float4 v = in[i];
    out[2 * i]     = __floats2half2_rn(v.x, v.y);
    out[2 * i + 1] = __floats2half2_rn(v.z, v.w);
}

// ======================= concat heads weights =======================
__global__ void concat_heads(const float* __restrict__ cw,  const float* __restrict__ cb,
                             const float* __restrict__ bw,  const float* __restrict__ bb_,
                             const float* __restrict__ ycw, const float* __restrict__ ycb,
                             const float* __restrict__ yrw, const float* __restrict__ yrb,
                             const float* __restrict__ hw,  const float* __restrict__ hb) {
    int idx = blockIdx.x * blockDim.x + threadIdx.x;
    if (idx >= FC * NP) return;
    int k = idx >> 7, n = idx & 127;
    float v = 0.f;
    if (n < 4)        v = cw [k * 4  + n];
    else if (n < 22)  v = bw [k * 18 + n - 4];
    else if (n < 58)  v = ycw[k * 36 + n - 22];
    else if (n < 94)  v = yrw[k * 36 + n - 58];
    else if (n < 100) v = hw [k * 6  + n - 94];
    g_Wcat[idx] = v;
    if (k == 0) {
        float bv = 0.f;
        if (n < 4)        bv = cb [n];
        else if (n < 22)  bv = bb_[n - 4];
        else if (n < 58)  bv = ycb[n - 22];
        else if (n < 94)  bv = yrb[n - 58];
        else if (n < 100) bv = hb [n - 94];
        g_bcat[n] = bv;
    }
}

// ======================= ROI align: (roi, pyrow) blocks, fixed 4x4 taps ========
__global__ void roi_align_kernel(const float* __restrict__ bbox2d,
                                 const int* __restrict__ anchor) {
    int roi = blockIdx.x;
    int py  = blockIdx.y;
    int b   = roi / N_ROI;
    int tid = threadIdx.x;   // 0..127

    __shared__ int   xs_p0[SAMP], xs_p1[SAMP];
    __shared__ float xs_l[SAMP], xs_v[SAMP];
    __shared__ int   ys_p0[2], ys_p1[2];
    __shared__ float ys_l[2], ys_v[2];
    __shared__ int   ox[7][4];
    __shared__ float wxs[7][4];
    __shared__ int   oy[4];
    __shared__ float wys[4];

    int level = anchor[roi] / 3;
    float scale = (level == 0) ? 0.25f : (level == 1) ? 0.125f : 0.0625f;
    int   H     = (level == 0) ? 128   : (level == 1) ? 64     : 32;
    const __half* F = (level == 0) ? g_f0 : (level == 1) ? g_f1 : g_f2;
    const __half2* F2 = (const __half2*)(F + (size_t)b * H * H * C_CH);

    if (tid < 16) {
        bool isY = tid >= 14;
        int axis = isY ? 0 : 1;        // 0 = y, 1 = x
        int j    = isY ? (2 * py + (tid - 14)) : tid;
        float cy = bbox2d[roi*4+0], cx = bbox2d[roi*4+1];
        float hh = bbox2d[roi*4+2], ww = bbox2d[roi*4+3];
        float lo_ = (axis == 0) ? (cy - 0.5f*hh) : (cx - 0.5f*ww);
        float hi_ = (axis == 0) ? (cy + 0.5f*hh) : (cx + 0.5f*ww);
        float start = lo_ * scale - 0.5f;
        float bs    = (hi_ - lo_) * scale / (float)RES;
        float g     = ((float)j + 0.5f) * 0.5f;
        float pos   = start + g * bs;
        float valid = (pos > -1.0f && pos < (float)H) ? 1.0f : 0.0f;
        float p  = fminf(fmaxf(pos, 0.0f), (float)(H - 1));
        int  p0  = (int)floorf(p);
        int  p1  = min(p0 + 1, H - 1);
        if (isY) {
            int s = tid - 14;
            ys_p0[s] = p0; ys_p1[s] = p1;
            ys_l[s] = p - (float)p0; ys_v[s] = valid;
        } else {
            xs_p0[j] = p0; xs_p1[j] = p1;
            xs_l[j] = p - (float)p0; xs_v[j] = valid;
        }
    }
    __syncthreads();

    if (tid < 8) {
        if (tid < 7) {
            int px = tid;
            int Cw = C_CH / 2;
#pragma unroll
            for (int s = 0; s < 2; s++) {
                int j = 2 * px + s;
                ox[px][2*s]   = xs_p0[j] * Cw;  wxs[px][2*s]   = (1.f - xs_l[j]) * xs_v[j];
                ox[px][2*s+1] = xs_p1[j] * Cw;  wxs[px][2*s+1] = xs_l[j] * xs_v[j];
            }
        } else {
            int Hw = H * (C_CH / 2);
#pragma unroll
            for (int s = 0; s < 2; s++) {
                oy[2*s]   = ys_p0[s] * Hw;  wys[2*s]   = (1.f - ys_l[s]) * ys_v[s] * 0.25f;
                oy[2*s+1] = ys_p1[s] * Hw;  wys[2*s+1] = ys_l[s] * ys_v[s] * 0.25f;
            }
        }
    }
    __syncthreads();

    int c2 = tid;
    const __half2* base = F2 + c2;
    const __half2* ra[4] = {base + oy[0], base + oy[1], base + oy[2], base + oy[3]};
    float wya[4] = {wys[0], wys[1], wys[2], wys[3]};
    __half2* xout = (__half2*)(g_Xh + (size_t)roi * K1 + (size_t)py * 7 * C_CH) + c2;

#pragma unroll 1
    for (int px = 0; px < 7; px++) {
        int   o0 = ox[px][0], o1 = ox[px][1], o2 = ox[px][2], o3 = ox[px][3];
        float w0 = wxs[px][0], w1 = wxs[px][1], w2 = wxs[px][2], w3 = wxs[px][3];
        float v0 = 0.f, v1 = 0.f;
#pragma unroll
        for (int iy = 0; iy < 4; iy++) {
            const __half2* r = ra[iy];
            float wy = wya[iy];
            float2 f0 = __half22float2(r[o0]);
            float2 f1 = __half22float2(r[o1]);
            float2 f2 = __half22float2(r[o2]);
            float2 f3 = __half22float2(r[o3]);
            v0 += wy * (w0 * f0.x + w1 * f1.x + w2 * f2.x + w3 * f3.x);
            v1 += wy * (w0 * f0.y + w1 * f1.y + w2 * f2.y + w3 * f3.y);
        }
        xout[px * (C_CH / 2)] = __floats2half2_rn(v0, v1);
    }
}

// ======================= fp16 HMMA GEMM (output type templated) ================
#define SA_STRIDE 80               // 32 halves (64B) + 16B pad
#define SB_STRIDE 272              // 128 halves (256B) + 16B pad
#define A_TILE (128 * SA_STRIDE)   // 10240
#define B_TILE (32 * SB_STRIDE)    // 8704
#define STAGE_B (A_TILE + B_TILE)  // 18944
#define GEMM_SMEM (4 * STAGE_B)    // 75776

template<typename TO>
__global__ void __launch_bounds__(256)
gemm_f16(const __half* __restrict__ A, const __half* __restrict__ W,
         const float* __restrict__ bias, TO* __restrict__ Cc,
         int N, int K) {
    extern __shared__ char smem[];
    uint32_t sb = smem_u32(smem);
    int tid = threadIdx.x, wid = tid >> 5, lid = tid & 31;
    int mBase = blockIdx.y * 128, nBase = blockIdx.x * 128;
    int kh = wid >> 2;
    int wm = (wid >> 1) & 1, wn = wid & 1;

    float acc[4][8][4];
#pragma unroll
    for (int i = 0; i < 4; i++)
#pragma unroll
        for (int j = 0; j < 8; j++)
#pragma unroll
            for (int q = 0; q < 4; q++) acc[i][j][q] = 0.f;

    const int nIter = K >> 5;

    auto load_stage = [&](int iter, int stage) {
        int k0 = iter * 32;
        uint32_t stBase = sb + stage * STAGE_B;
#pragma unroll
        for (int i = 0; i < 2; i++) {
            int idx = tid + i * 256;
            int row = idx >> 2, ck = idx & 3;
            cp_async16(stBase + row * SA_STRIDE + ck * 16,
                       A + (size_t)(mBase + row) * K + k0 + ck * 8);
        }
#pragma unroll
        for (int i = 0; i < 2; i++) {
            int idx = tid + i * 256;
            int row = idx >> 4, ck = idx & 15;
            cp_async16(stBase + A_TILE + row * SB_STRIDE + ck * 16,
                       W + (size_t)(k0 + row) * N + nBase + ck * 8);
        }
        cp_commit();
    };

    load_stage(0, 0);
    if (nIter > 1) load_stage(1, 1);
    if (nIter > 2) load_stage(2, 2);

    for (int it = 0; it < nIter; it++) {
        int stage = it & 3;
        if (it + 3 < nIter) { load_stage(it + 3, (it + 3) & 3); cp_wait<3>(); }
        else if (it + 2 < nIter) cp_wait<2>();
        else if (it + 1 < nIter) cp_wait<1>();
        else cp_wait<0>();
        __syncthreads();

        uint32_t stBase = sb + stage * STAGE_B;
        uint32_t aB = stBase;
        uint32_t bB = stBase + A_TILE;

        uint32_t ah[4][4], bh[8][2];
#pragma unroll
        for (int mt = 0; mt < 4; mt++) {
            uint32_t off = (uint32_t)(wm * 64 + mt * 16 + (lid & 15)) * SA_STRIDE
                         + kh * 32 + (lid >> 4) * 16;
            ldsm_x4(ah[mt], aB + off);
        }
#pragma unroll
        for (int np = 0; np < 4; np++) {
            uint32_t off = (uint32_t)(kh * 16 + (lid & 15)) * SB_STRIDE
                         + (wn * 64 + np * 16 + (lid >> 4) * 8) * 2;
            uint32_t t[4];
            ldsm_x4_t(t, bB + off);
            bh[np*2][0] = t[0]; bh[np*2][1] = t[1];
            bh[np*2+1][0] = t[2]; bh[np*2+1][1] = t[3];
        }
#pragma unroll
        for (int mt = 0; mt < 4; mt++)
#pragma unroll
            for (int nt = 0; nt < 8; nt++)
                mma16816(acc[mt][nt], ah[mt], bh[nt]);
        __syncthreads();
    }

    int tile = wm * 2 + wn;
    float* ep = (float*)(smem + tile * 16384);
    if (kh == 1) {
#pragma unroll
        for (int mt = 0; mt < 4; mt++)
#pragma unroll
            for (int nt = 0; nt < 8; nt++)
                *(float4*)(ep + ((mt * 8 + nt) * 32 + lid) * 4) = *(float4*)acc[mt][nt];
    }
    __syncthreads();
    if (kh == 0) {
        int g = lid >> 2, ti = lid & 3;
#pragma unroll
        for (int mt = 0; mt < 4; mt++) {
            int m0 = mBase + wm * 64 + mt * 16 + g;
#pragma unroll
            for (int nt = 0; nt < 8; nt++) {
                float4 p = *(float4*)(ep + ((mt * 8 + nt) * 32 + lid) * 4);
                int n0 = nBase + wn * 64 + nt * 8 + ti * 2;
                float b0 = bias[n0], b1 = bias[n0 + 1];
                float c00 = acc[mt][nt][0] + p.x + b0;
                float c01 = acc[mt][nt][1] + p.y + b1;
                float c10 = acc[mt][nt][2] + p.z + b0;
                float c11 = acc[mt][nt][3] + p.w + b1;
                if (sizeof(TO) == 2) {
                    *(__half2*)((__half*)Cc + (size_t)m0 * N + n0) = __floats2half2_rn(c00, c01);
                    *(__half2*)((__half*)Cc + (size_t)(m0 + 8) * N + n0) = __floats2half2_rn(c10, c11);
                } else {
                    *(float2*)((float*)Cc + (size_t)m0 * N + n0) = make_float2(c00, c01);
                    *(float2*)((float*)Cc + (size_t)(m0 + 8) * N + n0) = make_float2(c10, c11);
                }
            }
        }
    }
}

// ======================= BN stats (fp16 input) =======================
__global__ void bn_stats_part_h(const __half2* __restrict__ Y) {
    int c0 = blockIdx.x * 32;           // 32 columns = 16 half2
    int seg = blockIdx.y;
    int tid = threadIdx.x;              // 256 = 16 col-pairs x 16 rows
    int c2 = tid & 15, r0 = tid >> 4;
    float s0 = 0.f, q0 = 0.f, s1 = 0.f, q1 = 0.f;
    int rBase = seg * 256;
    for (int r = r0; r < 256; r += 16) {
        float2 v = __half22float2(Y[(size_t)(rBase + r) * (FC/2) + c0/2 + c2]);
        s0 += v.x; q0 += v.x * v.x;
        s1 += v.y; q1 += v.y * v.y;
    }
    __shared__ float sh[4][16][16];
    sh[0][r0][c2] = s0; sh[1][r0][c2] = q0; sh[2][r0][c2] = s1; sh[3][r0][c2] = q1;
    __syncthreads();
    if (r0 == 0) {
        float ts0 = 0.f, tq0 = 0.f, ts1 = 0.f, tq1 = 0.f;
#pragma unroll
        for (int i = 0; i < 16; i++) {
            ts0 += sh[0][i][c2]; tq0 += sh[1][i][c2];
            ts1 += sh[2][i][c2]; tq1 += sh[3][i][c2];
        }
        g_bnp[seg][0][c0 + 2*c2]     = ts0;
        g_bnp[seg][1][c0 + 2*c2]     = tq0;
        g_bnp[seg][0][c0 + 2*c2 + 1] = ts1;
        g_bnp[seg][1][c0 + 2*c2 + 1] = tq1;
    }
}

// ======================= BN stats (fp32 input) =======================
__global__ void bn_stats_part(const float* __restrict__ Y) {
    int c0 = blockIdx.x * 32;
    int seg = blockIdx.y;
    int tid = threadIdx.x;
    int c = tid % 32, r0 = tid / 32;
    float sm = 0.f, s2 = 0.f;
    int rBase = seg * 256;
    for (int r = r0; r < 256; r += 8) {
        float v = Y[(size_t)(rBase + r) * FC + c0 + c];
        sm += v; s2 += v * v;
    }
    __shared__ float sh[2][8][32];
    sh[0][r0][c] = sm; sh[1][r0][c] = s2;
    __syncthreads();
    if (r0 == 0) {
        float ts = 0.f, ts2 = 0.f;
#pragma unroll
        for (int i = 0; i < 8; i++) { ts += sh[0][i][c]; ts2 += sh[1][i][c]; }
        g_bnp[seg][0][c0 + c] = ts;
        g_bnp[seg][1][c0 + c] = ts2;
    }
}

__global__ void bn_finalize(const float* __restrict__ g, const float* __restrict__ b,
                            float* __restrict__ s, float* __restrict__ t) {
    int c = blockIdx.x * blockDim.x + threadIdx.x;
    if (c >= FC) return;
    float ts = 0.f, ts2 = 0.f;
#pragma unroll
    for (int i = 0; i < 8; i++) { ts += g_bnp[i][0][c]; ts2 += g_bnp[i][1][c]; }
    float m = ts / (float)M_TOT;
    float var = ts2 / (float)M_TOT - m * m;
    float sc = rsqrtf(var + 1e-5f) * g[c];
    s[c] = sc;
    t[c] = b[c] - m * sc;
}

// BN apply + ReLU, fp16 in -> fp16 out
__global__ void bn_apply_relu_hh(const __half2* __restrict__ Y,
                                 const float* __restrict__ s, const float* __restrict__ t,
                                 __half2* __restrict__ out) {
    int i = blockIdx.x * blockDim.x + threadIdx.x;
    if (i >= M_TOT * FC / 2) return;
    int c = (i * 2) & (FC - 1);
    float2 v = __half22float2(Y[i]);
    float a0 = fmaxf(v.x * s[c + 0] + t[c + 0], 0.f);
    float a1 = fmaxf(v.y * s[c + 1] + t[c + 1], 0.f);
    out[i] = __floats2half2_rn(a0, a1);
}

// ======================= heads: k-split GEMM with fused BN2 =======================
#define SY_STRIDE 65
#define HEADS_SMEM (128 * SY_STRIDE * 4 + 64 * NP * 4)

__global__ void __launch_bounds__(256) heads_part(const float* __restrict__ Y2) {
    extern __shared__ char hs[];
    float* sY = (float*)hs;
    float* sW = (float*)(hs + 128 * SY_STRIDE * 4);
    int tid = threadIdx.x;
    int m0 = blockIdx.x * 128;
    int ks = blockIdx.y;
    int cg = tid & 15, rt = tid >> 4;

    float acc[8][8];
#pragma unroll
    for (int i = 0; i < 8; i++)
#pragma unroll
        for (int j = 0; j < 8; j++) acc[i][j] = 0.f;

    for (int ch = 0; ch < 2; ch++) {
        int k0 = ks * 128 + ch * 64;
        if (ch) __syncthreads();
#pragma unroll
        for (int i = 0; i < 8; i++) {
            int i4 = tid + i * 256;
            int row = i4 >> 4, c4 = i4 & 15;
            float4 v = *(const float4*)(Y2 + (size_t)(m0 + row) * FC + k0 + c4 * 4);
            int kk = k0 + c4 * 4;
            float* d = sY + row * SY_STRIDE + c4 * 4;
            d[0] = fmaxf(v.x * g_s[kk + 0] + g_t[kk + 0], 0.f);
            d[1] = fmaxf(v.y * g_s[kk + 1] + g_t[kk + 1], 0.f);
            d[2] = fmaxf(v.z * g_s[kk + 2] + g_t[kk + 2], 0.f);
            d[3] = fmaxf(v.w * g_s[kk + 3] + g_t[kk + 3], 0.f);
        }
#pragma unroll
        for (int i = 0; i < 8; i++) {
            int i4 = tid + i * 256;
            int kk = i4 >> 5, c4 = i4 & 31;
            *(float4*)(sW + kk * NP + c4 * 4) =
                *(const float4*)(g_Wcat + (size_t)(k0 + kk) * NP + c4 * 4);
        }
        __syncthreads();

        for (int k = 0; k < 64; k++) {
            float yv[8];
#pragma unroll
            for (int i = 0; i < 8; i++) yv[i] = sY[(rt + 16 * i) * SY_STRIDE + k];
#pragma unroll
            for (int j = 0; j < 4; j++) {
                float2 wv = *(float2*)(sW + k * NP + cg * 2 + 32 * j);
#pragma unroll
                for (int i = 0; i < 8; i++) {
                    acc[i][j * 2]     += yv[i] * wv.x;
                    acc[i][j * 2 + 1] += yv[i] * wv.y;
                }
            }
        }
    }

#pragma unroll
    for (int i = 0; i < 8; i++) {
        int m = m0 + rt + 16 * i;
#pragma unroll
        for (int j = 0; j < 4; j++) {
            *(float2*)&g_hp[ks][m][cg * 2 + 32 * j] =
                make_float2(acc[i][j * 2], acc[i][j * 2 + 1]);
        }
    }
}

__global__ void heads_reduce(float* __restrict__ out) {
    int idx = blockIdx.x * blockDim.x + threadIdx.x;
    if (idx >= M_TOT * OUT_D) return;
    int m = idx / OUT_D, c = idx % OUT_D;
    float a = g_bcat[c];
#pragma unroll
    for (int s = 0; s < 8; s++) a += g_hp[s][m][c];
    out[idx] = a;
}

// ======================= launch =======================
extern "C" void kernel_launch(void* const* d_in, const int* in_sizes, int n_in,
                              void* d_out, int out_size) {
    const float* feat0    = (const float*)d_in[0];
    const float* feat1    = (const float*)d_in[1];
    const float* feat2    = (const float*)d_in[2];
    const float* bbox2d   = (const float*)d_in[3];
    const int*   anchor   = (const int*)  d_in[4];
    const float* fc1_w    = (const float*)d_in[5];
    const float* fc1_b    = (const float*)d_in[6];
    const float* bn1_g    = (const float*)d_in[7];
    const float* bn1_b    = (const float*)d_in[8];
    const float* fc2_w    = (const float*)d_in[9];
    const float* fc2_b    = (const float*)d_in[10];
    const float* bn2_g    = (const float*)d_in[11];
    const float* bn2_b    = (const float*)d_in[12];
    const float* cate_w   = (const float*)d_in[13];
    const float* cate_b   = (const float*)d_in[14];
    const float* bbox3d_w = (const float*)d_in[15];
    const float* bbox3d_b = (const float*)d_in[16];
    const float* yawc_w   = (const float*)d_in[17];
    const float* yawc_b   = (const float*)d_in[18];
    const float* yawr_w   = (const float*)d_in[19];
    const float* yawr_b   = (const float*)d_in[20];
    const float* hgt_w    = (const float*)d_in[21];
    const float* hgt_b    = (const float*)d_in[22];
    float* out = (float*)d_out;

    float *pY2, *ps, *pt;
    __half *pXh, *pW1h, *pW2h, *pA2h, *pY1h;
    cudaGetSymbolAddress((void**)&pXh, g_Xh);
    cudaGetSymbolAddress((void**)&pW1h, g_W1h);
    cudaGetSymbolAddress((void**)&pW2h, g_W2h);
    cudaGetSymbolAddress((void**)&pA2h, g_A2h);
    cudaGetSymbolAddress((void**)&pY1h, g_Y1h);
    cudaGetSymbolAddress((void**)&pY2, g_Y2);
    cudaGetSymbolAddress((void**)&ps, g_s);
    cudaGetSymbolAddress((void**)&pt, g_t);

    cudaFuncSetAttribute(gemm_f16<__half>, cudaFuncAttributeMaxDynamicSharedMemorySize, GEMM_SMEM);
    cudaFuncSetAttribute(gemm_f16<float>,  cudaFuncAttributeMaxDynamicSharedMemorySize, GEMM_SMEM);
    cudaFuncSetAttribute(heads_part, cudaFuncAttributeMaxDynamicSharedMemorySize, HEADS_SMEM);

    cudaStream_t s0 = 0;

    // fork: weight prep on aux stream, hidden under transpose+roi
    cudaEventRecord(e_fork, s0);
    cudaStreamWaitEvent(s_aux1, e_fork, 0);
    w1_perm_h<<<K1, 256, 0, s_aux1>>>((const float4*)fc1_w, (__half2*)pW1h);
    w_to_h4<<<(FC*FC/4 + 255)/256, 256, 0, s_aux1>>>((const float4*)fc2_w, (__half2*)pW2h, FC*FC/4);
    concat_heads<<<(FC*NP + 255)/256, 256, 0, s_aux1>>>(cate_w, cate_b, bbox3d_w, bbox3d_b,
                                                        yawc_w, yawc_b, yawr_w, yawr_b, hgt_w, hgt_b);
    cudaEventRecord(e_wprep, s_aux1);

    // main chain
    transpose_all<<<dim3(672, 8, B_SZ), dim3(32, 8), 0, s0>>>(feat0, feat1, feat2);
    roi_align_kernel<<<dim3(M_TOT, 7), 128, 0, s0>>>(bbox2d, anchor);

    cudaStreamWaitEvent(s0, e_wprep, 0);   // join weight prep

    // FC1 (K = 12544), fp16 out
    gemm_f16<__half><<<dim3(FC/128, M_TOT/128), 256, GEMM_SMEM, s0>>>(pXh, pW1h, fc1_b, pY1h, FC, K1);
    bn_stats_part_h<<<dim3(FC/32, 8), 256, 0, s0>>>((const __half2*)pY1h);
    bn_finalize<<<FC/256, 256, 0, s0>>>(bn1_g, bn1_b, ps, pt);
    bn_apply_relu_hh<<<(M_TOT*FC/2 + 255)/256, 256, 0, s0>>>((const __half2*)pY1h, ps, pt, (__half2*)pA2h);

    // FC2 (K = 1024), fp32 out
    gemm_f16<float><<<dim3(FC/128, M_TOT/128), 256, GEMM_SMEM, s0>>>(pA2h, pW2h, fc2_b, pY2, FC, FC);
    bn_stats_part<<<dim3(FC/32, 8), 256, 0, s0>>>(pY2);
    bn_finalize<<<FC/256, 256, 0, s0>>>(bn2_g, bn2_b, ps, pt);

    // heads: BN2 fused, k-split partials + reduce
    heads_part<<<dim3(M_TOT/128, 8), 256, HEADS_SMEM, s0>>>(pY2);
    heads_reduce<<<(M_TOT*OUT_D + 255)/256, 256, 0, s0>>>(out);
}